// round 15
// baseline (speedup 1.0000x reference)
#include <cuda_runtime.h>
#include <cuda_bf16.h>
#include <math.h>
#include <stdint.h>

#define BB 32
#define TT 64
#define FF 128
#define DD 64
#define HH 4
#define KK 32
// (1/sqrt(32)) * log2(e): softmax in log2 domain with ex2
#define QSCALE (0.17677669529663687f * 1.4426950408889634f)

// Pre-split weight buffer: [side][head][9472 words as uint4]
// per head: [0,3456) WCH | [3456,6912) WCL | [6912,8192) WOH | [8192,9472) WOL
// as uint4: WC = [0,1728), WO = [1728,2368)
__device__ uint4 g_w[2][4][2368];

__device__ __forceinline__ float ex2f(float x) {
    float y;
    asm("ex2.approx.ftz.f32 %0, %1;" : "=f"(y) : "f"(x));
    return y;
}

// Split two fp32 into packed bf16 hi-pair and lo-pair (v ~= hi + lo, err ~2^-18).
__device__ __forceinline__ void split_pk(float v0, float v1, uint32_t& hi, uint32_t& lo) {
    uint32_t h;
    asm("cvt.rn.bf16x2.f32 %0, %1, %2;" : "=r"(h) : "f"(v1), "f"(v0));
    float h0f = __uint_as_float(h << 16);
    float h1f = __uint_as_float(h & 0xffff0000u);
    float l0 = v0 - h0f;
    float l1 = v1 - h1f;
    uint32_t l;
    asm("cvt.rn.bf16x2.f32 %0, %1, %2;" : "=r"(l) : "f"(l1), "f"(l0));
    hi = h;
    lo = l;
}

// m16n8k16 bf16 mma, C += A*B (fp32 accum).
__device__ __forceinline__ void mmabf(float* c, const uint32_t* a, const uint32_t* b) {
    asm volatile(
        "mma.sync.aligned.m16n8k16.row.col.f32.bf16.bf16.f32 "
        "{%0,%1,%2,%3}, {%4,%5,%6,%7}, {%8,%9}, {%0,%1,%2,%3};"
        : "+f"(c[0]), "+f"(c[1]), "+f"(c[2]), "+f"(c[3])
        : "r"(a[0]), "r"(a[1]), "r"(a[2]), "r"(a[3]), "r"(b[0]), "r"(b[1]));
}
// 3-term compensated product, single accumulator (used where chains abound).
__device__ __forceinline__ void mma3(float* c, const uint32_t* ah, const uint32_t* al,
                                     const uint32_t* bh, const uint32_t* bl) {
    mmabf(c, al, bh);
    mmabf(c, ah, bl);
    mmabf(c, ah, bh);
}
// Dual-accumulator variant: main chain (ah*bh) and comp chain (al*bh + ah*bl)
// kept in separate accumulators to double independent HMMA chains.
__device__ __forceinline__ void mma3d(float* cm, float* cc,
                                      const uint32_t* ah, const uint32_t* al,
                                      const uint32_t* bh, const uint32_t* bl) {
    mmabf(cc, al, bh);
    mmabf(cc, ah, bl);
    mmabf(cm, ah, bh);
}

// ldmatrix.x4
__device__ __forceinline__ void ldsm4(uint32_t addr, uint32_t* r) {
    asm volatile("ldmatrix.sync.aligned.m8n8.x4.shared.b16 {%0,%1,%2,%3}, [%4];"
        : "=r"(r[0]), "=r"(r[1]), "=r"(r[2]), "=r"(r[3])
        : "r"(addr));
}

// B hi+lo fragment pair via one LDSM.x4.
__device__ __forceinline__ void ldB4(uint32_t base, uint32_t lodelta, int W, int off_w,
                                     int lane, uint32_t* bh, uint32_t* bl) {
    uint32_t a = base + (uint32_t)off_w * 4u
               + (uint32_t)(lane & 7) * (uint32_t)(W * 4)
               + (uint32_t)((lane >> 3) & 1) * 16u
               + (uint32_t)((lane >> 4) & 1) * lodelta;
    uint32_t r[4];
    ldsm4(a, r);
    bh[0] = r[0]; bh[1] = r[1]; bl[0] = r[2]; bl[1] = r[3];
}

// A fragment via one LDSM.x4.
__device__ __forceinline__ void ldA4(uint32_t base, int W, int off_w, int lane, uint32_t* a) {
    uint32_t ad = base + (uint32_t)off_w * 4u
                + (uint32_t)((lane & 7) + ((lane >> 3) & 1) * 8) * (uint32_t)(W * 4)
                + (uint32_t)((lane >> 4) & 1) * 16u;
    ldsm4(ad, a);
}

// Feature S-chunk mma with dual accumulators (8 independent chains).
__device__ __forceinline__ void sfeat_chunk(
    uint32_t KTb, int c, int lane,
    const uint32_t QAh[2][4], const uint32_t QAl[2][4], float cS[4][4])
{
    float cC[4][4];
#pragma unroll
    for (int j = 0; j < 4; j++)
#pragma unroll
        for (int i = 0; i < 4; i++) { cS[j][i] = 0.f; cC[j][i] = 0.f; }
#pragma unroll
    for (int kk = 0; kk < 2; kk++) {
#pragma unroll
        for (int j = 0; j < 4; j++) {
            uint32_t bh2[2], bl2[2];
            ldB4(KTb, 10240u, 20, (c * 4 + j) * 8 * 20 + kk * 8, lane, bh2, bl2);
            mma3d(cS[j], cC[j], QAh[kk], QAl[kk], bh2, bl2);
        }
    }
#pragma unroll
    for (int j = 0; j < 4; j++)
#pragma unroll
        for (int i = 0; i < 4; i++) cS[j][i] += cC[j][i];
}

// ---------------------------------------------------------------------------
// Prep kernel: split all weights once into g_w (smem-staging layout).
// ---------------------------------------------------------------------------
__global__ void prep_kernel(
    const float* __restrict__ tqw, const float* __restrict__ tkw,
    const float* __restrict__ tvw, const float* __restrict__ tow,
    const float* __restrict__ fqw, const float* __restrict__ fkw,
    const float* __restrict__ fvw, const float* __restrict__ fow)
{
    int side = blockIdx.x >> 2, h = blockIdx.x & 3;
    const float* wq = side ? fqw : tqw;
    const float* wk = side ? fkw : tkw;
    const float* wv = side ? fvw : tvw;
    const float* wo = side ? fow : tow;
    uint32_t* dstw = (uint32_t*)&g_w[side][h][0];
    int tid = threadIdx.x;
    for (int i = tid; i < 96 * 32; i += 256) {
        int n = i % 96, dp = i / 96;
        const float* src = (n < 32) ? wq : (n < 64) ? wk : wv;
        int nn = n & 31;
        float v0 = src[(2 * dp) * 128 + h * 32 + nn];
        float v1 = src[(2 * dp + 1) * 128 + h * 32 + nn];
        split_pk(v0, v1, dstw[n * 36 + dp], dstw[3456 + n * 36 + dp]);
    }
    for (int i = tid; i < 64 * 16; i += 256) {
        int d = i & 63, kp = i >> 6;
        float v0 = wo[h * 2048 + (2 * kp) * 64 + d];
        float v1 = wo[h * 2048 + (2 * kp + 1) * 64 + d];
        split_pk(v0, v1, dstw[6912 + d * 20 + kp], dstw[8192 + d * 20 + kp]);
    }
}

// ---------------------------------------------------------------------------
// Feature body: id -> (b, t). 128 rows, 8 warps x 16 rows. atomicAdd into out.
// WC(h+1) prefetched after the KV barrier, overlapping S/PV tensor work.
// ---------------------------------------------------------------------------
__device__ __forceinline__ void feature_body(
    uint32_t* smw, int id,
    const float* __restrict__ x,
    const uint4* __restrict__ wsrc,
    const float* __restrict__ bq_g, const float* __restrict__ bk_g,
    const float* __restrict__ bv_g, const float* __restrict__ bo_g,
    float* __restrict__ out)
{
    uint32_t* XH  = smw;            // 128 x 36
    uint32_t* XL  = smw + 4608;
    uint32_t* KTH = smw + 18688;    // 128 x 20
    uint32_t* KTL = smw + 21248;
    uint32_t* VTH = smw + 23808;    // 32 x 68
    uint32_t* VTL = smw + 25984;    // -> 28160

    const uint32_t sb = (uint32_t)__cvta_generic_to_shared(smw);
    const uint32_t XHb = sb;                    // XL delta = 18432 B
    const uint32_t WCb = sb + 9216u * 4u;       // lo delta = 13824 B
    const uint32_t WOb = sb + 16128u * 4u;      // lo delta = 5120 B
    const uint32_t KTb = sb + 18688u * 4u;      // lo delta = 10240 B
    const uint32_t VTb = sb + 23808u * 4u;      // lo delta = 8704 B

    const int tid  = threadIdx.x;
    const int lane = tid & 31;
    const int w    = tid >> 5;
    const int g    = lane >> 2;
    const int t    = lane & 3;
    const int b    = id >> 6;
    const int tt   = id & 63;
    const int row0 = w * 16;
    const int rrA  = row0 + g, rrB = row0 + g + 8;

    // Stage x slice + WC(0)
    {
        const float* xp = x + (size_t)(b * TT + tt) * (FF * DD);
        for (int i = tid; i < FF * 32; i += 256) {
            int row = i >> 5, dp = i & 31;
            float2 v = *(const float2*)(xp + row * 64 + 2 * dp);
            split_pk(v.x, v.y, XH[row * 36 + dp], XL[row * 36 + dp]);
        }
        uint4* dstv = (uint4*)(smw + 9216);
        for (int i = tid; i < 1728; i += 256) dstv[i] = wsrc[i];
    }

    float oacc[8][4];
#pragma unroll
    for (int j = 0; j < 8; j++)
#pragma unroll
        for (int i = 0; i < 4; i++) oacc[j][i] = 0.f;

    for (int h = 0; h < HH; h++) {
        __syncthreads();   // WC(h)/x writes visible; prior head's WO reads done
        // Stage WO(h) (small; LDG latency overlaps GEMM1 below, read after KV sync)
        {
            const uint4* srcv = wsrc + (size_t)h * 2368 + 1728;
            uint4* dstv = (uint4*)(smw + 16128);
            for (int i = tid; i < 640; i += 256) dstv[i] = srcv[i];
        }

        // --- GEMM1: [16 rows] x [k=64] x [n=96] ---
        float c12[12][4];
#pragma unroll
        for (int j = 0; j < 12; j++)
#pragma unroll
            for (int i = 0; i < 4; i++) c12[j][i] = 0.f;
        for (int kk = 0; kk < 4; kk++) {
            uint32_t ah[4], al[4];
            ldA4(XHb, 36, row0 * 36 + kk * 8, lane, ah);
            ldA4(XHb + 18432u, 36, row0 * 36 + kk * 8, lane, al);
#pragma unroll
            for (int j = 0; j < 12; j++) {
                uint32_t bh2[2], bl2[2];
                ldB4(WCb, 13824u, 36, j * 8 * 36 + kk * 8, lane, bh2, bl2);
                mma3(c12[j], ah, al, bh2, bl2);
            }
        }
        // Epilogue: Q -> regs, K -> smem, V -> smem transposed
        uint32_t QAh[2][4], QAl[2][4];
#pragma unroll
        for (int j = 0; j < 4; j++) {
            int cc = j * 8 + 2 * t;
            float b0 = bq_g[h * 32 + cc], b1 = bq_g[h * 32 + cc + 1];
            float v0 = (c12[j][0] + b0) * QSCALE, v1 = (c12[j][1] + b1) * QSCALE;
            float v2 = (c12[j][2] + b0) * QSCALE, v3 = (c12[j][3] + b1) * QSCALE;
            int kc = j >> 1, e = j & 1;
            split_pk(v0, v1, QAh[kc][2 * e],     QAl[kc][2 * e]);
            split_pk(v2, v3, QAh[kc][2 * e + 1], QAl[kc][2 * e + 1]);
        }
#pragma unroll
        for (int j = 4; j < 8; j++) {
            int cc = (j - 4) * 8 + 2 * t;
            float b0 = bk_g[h * 32 + cc], b1 = bk_g[h * 32 + cc + 1];
            int kp = cc >> 1;
            split_pk(c12[j][0] + b0, c12[j][1] + b1, KTH[rrA * 20 + kp], KTL[rrA * 20 + kp]);
            split_pk(c12[j][2] + b0, c12[j][3] + b1, KTH[rrB * 20 + kp], KTL[rrB * 20 + kp]);
        }
        {
            __nv_bfloat16* vh = reinterpret_cast<__nv_bfloat16*>(VTH);
            __nv_bfloat16* vl = reinterpret_cast<__nv_bfloat16*>(VTL);
#pragma unroll
            for (int j = 8; j < 12; j++) {
                int vk = (j - 8) * 8 + 2 * t;
                float b0 = bv_g[h * 32 + vk], b1 = bv_g[h * 32 + vk + 1];
                float vv[4] = {c12[j][0] + b0, c12[j][1] + b1, c12[j][2] + b0, c12[j][3] + b1};
                int   cl[4] = {vk, vk + 1, vk, vk + 1};
                int   rw[4] = {rrA, rrA, rrB, rrB};
#pragma unroll
                for (int q2 = 0; q2 < 4; q2++) {
                    __nv_bfloat16 hb = __float2bfloat16(vv[q2]);
                    float lf = vv[q2] - __bfloat162float(hb);
                    vh[cl[q2] * 136 + rw[q2]] = hb;
                    vl[cl[q2] * 136 + rw[q2]] = __float2bfloat16(lf);
                }
            }
        }
        __syncthreads();   // K/V + WO visible; GEMM1's WC reads complete

        // Prefetch WC(h+1): LDG/STS overlap the S/PV/outproj tensor work below.
        if (h < 3) {
            const uint4* srcv = wsrc + (size_t)(h + 1) * 2368;
            uint4* dstv = (uint4*)(smw + 9216);
            for (int i = tid; i < 1728; i += 256) dstv[i] = srcv[i];
        }

        // --- S = Q K^T, online softmax, fused PV; pipelined over 4 chunks ---
        float cP[4][4];
#pragma unroll
        for (int j = 0; j < 4; j++)
#pragma unroll
            for (int i = 0; i < 4; i++) cP[j][i] = 0.f;
        float mrA, mrB, sA, sB;
        float cSb[2][4][4];

        sfeat_chunk(KTb, 0, lane, QAh, QAl, cSb[0]);
#pragma unroll
        for (int c = 0; c < 4; c++) {
            float (*cS)[4] = cSb[c & 1];
            if (c < 3) sfeat_chunk(KTb, c + 1, lane, QAh, QAl, cSb[(c + 1) & 1]);

            float mA = cS[0][0], mB = cS[0][2];
#pragma unroll
            for (int j = 0; j < 4; j++) {
                mA = fmaxf(mA, fmaxf(cS[j][0], cS[j][1]));
                mB = fmaxf(mB, fmaxf(cS[j][2], cS[j][3]));
            }
            mA = fmaxf(mA, __shfl_xor_sync(0xffffffff, mA, 1));
            mA = fmaxf(mA, __shfl_xor_sync(0xffffffff, mA, 2));
            mB = fmaxf(mB, __shfl_xor_sync(0xffffffff, mB, 1));
            mB = fmaxf(mB, __shfl_xor_sync(0xffffffff, mB, 2));
            float nmA, nmB, chA = 0.f, chB = 0.f;
            if (c == 0) {
                nmA = mA; nmB = mB;
#pragma unroll
                for (int j = 0; j < 4; j++) {
                    cS[j][0] = ex2f(cS[j][0] - nmA); chA += cS[j][0];
                    cS[j][1] = ex2f(cS[j][1] - nmA); chA += cS[j][1];
                    cS[j][2] = ex2f(cS[j][2] - nmB); chB += cS[j][2];
                    cS[j][3] = ex2f(cS[j][3] - nmB); chB += cS[j][3];
                }
                sA = chA; sB = chB;
            } else {
                nmA = fmaxf(mrA, mA); nmB = fmaxf(mrB, mB);
                float scA = ex2f(mrA - nmA), scB = ex2f(mrB - nmB);
#pragma unroll
                for (int j = 0; j < 4; j++) {
                    cS[j][0] = ex2f(cS[j][0] - nmA); chA += cS[j][0];
                    cS[j][1] = ex2f(cS[j][1] - nmA); chA += cS[j][1];
                    cS[j][2] = ex2f(cS[j][2] - nmB); chB += cS[j][2];
                    cS[j][3] = ex2f(cS[j][3] - nmB); chB += cS[j][3];
                }
                sA = sA * scA + chA;
                sB = sB * scB + chB;
#pragma unroll
                for (int j = 0; j < 4; j++) {
                    cP[j][0] *= scA; cP[j][1] *= scA;
                    cP[j][2] *= scB; cP[j][3] *= scB;
                }
            }
            uint32_t ph[2][4], pl[2][4];
#pragma unroll
            for (int k0e = 0; k0e < 2; k0e++) {
                int j0 = 2 * k0e;
                split_pk(cS[j0][0],     cS[j0][1],     ph[k0e][0], pl[k0e][0]);
                split_pk(cS[j0][2],     cS[j0][3],     ph[k0e][1], pl[k0e][1]);
                split_pk(cS[j0 + 1][0], cS[j0 + 1][1], ph[k0e][2], pl[k0e][2]);
                split_pk(cS[j0 + 1][2], cS[j0 + 1][3], ph[k0e][3], pl[k0e][3]);
            }
            // PV for this chunk: dual accumulators, merged into cP.
            {
                float tM[4][4], tC[4][4];
#pragma unroll
                for (int j = 0; j < 4; j++)
#pragma unroll
                    for (int i = 0; i < 4; i++) { tM[j][i] = 0.f; tC[j][i] = 0.f; }
#pragma unroll
                for (int k0e = 0; k0e < 2; k0e++) {
                    int kkv = 2 * c + k0e;
#pragma unroll
                    for (int j = 0; j < 4; j++) {
                        uint32_t bh2[2], bl2[2];
                        ldB4(VTb, 8704u, 68, j * 8 * 68 + kkv * 8, lane, bh2, bl2);
                        mma3d(tM[j], tC[j], ph[k0e], pl[k0e], bh2, bl2);
                    }
                }
#pragma unroll
                for (int j = 0; j < 4; j++)
#pragma unroll
                    for (int i = 0; i < 4; i++) cP[j][i] += tM[j][i] + tC[j][i];
            }
            mrA = nmA; mrB = nmB;
        }
        sA += __shfl_xor_sync(0xffffffff, sA, 1);
        sA += __shfl_xor_sync(0xffffffff, sA, 2);
        sB += __shfl_xor_sync(0xffffffff, sB, 1);
        sB += __shfl_xor_sync(0xffffffff, sB, 2);
        float invA = __fdividef(1.f, sA), invB = __fdividef(1.f, sB);
#pragma unroll
        for (int j = 0; j < 4; j++) {
            cP[j][0] *= invA; cP[j][1] *= invA;
            cP[j][2] *= invB; cP[j][3] *= invB;
        }

        // O -> regs, outproj accumulate
        uint32_t OAh[2][4], OAl[2][4];
#pragma unroll
        for (int j = 0; j < 4; j++) {
            int kc = j >> 1, e = j & 1;
            split_pk(cP[j][0], cP[j][1], OAh[kc][2 * e],     OAl[kc][2 * e]);
            split_pk(cP[j][2], cP[j][3], OAh[kc][2 * e + 1], OAl[kc][2 * e + 1]);
        }
#pragma unroll
        for (int kk = 0; kk < 2; kk++) {
#pragma unroll
            for (int j = 0; j < 8; j++) {
                uint32_t bh2[2], bl2[2];
                ldB4(WOb, 5120u, 20, j * 8 * 20 + kk * 8, lane, bh2, bl2);
                mma3(oacc[j], OAh[kk], OAl[kk], bh2, bl2);
            }
        }
    }

    // Deposit into out (zero-initialized by memset). rows = f, cols = d
#pragma unroll
    for (int j = 0; j < 8; j++) {
        int d0 = j * 8 + 2 * t;
        float bo0 = bo_g[d0], bo1 = bo_g[d0 + 1];
        size_t base0 = ((size_t)(b * TT + tt) * FF + rrA) * DD;
        size_t base1 = ((size_t)(b * TT + tt) * FF + rrB) * DD;
        atomicAdd(out + base0 + d0,     oacc[j][0] + bo0);
        atomicAdd(out + base0 + d0 + 1, oacc[j][1] + bo1);
        atomicAdd(out + base1 + d0,     oacc[j][2] + bo0);
        atomicAdd(out + base1 + d0 + 1, oacc[j][3] + bo1);
    }
}

// ---------------------------------------------------------------------------
// Temporal body: id -> (b, f-pair). 2 sub-blocks x 64 rows (T). atomicAdd out.
// ---------------------------------------------------------------------------
__device__ __forceinline__ void temporal_body(
    uint32_t* smw, int id,
    const float* __restrict__ x,
    const uint4* __restrict__ wsrc,
    const float* __restrict__ bq_g, const float* __restrict__ bk_g,
    const float* __restrict__ bv_g, const float* __restrict__ bo_g,
    float* __restrict__ out)
{
    uint32_t* XH  = smw;            // 2 x (64 x 36)
    uint32_t* XL  = smw + 4608;
    uint32_t* KTH = smw + 18688;    // 2 x (64 x 20)
    uint32_t* KTL = smw + 21248;
    uint32_t* VTH = smw + 23808;    // 2 x (32 x 36)
    uint32_t* VTL = smw + 26112;    // -> 28416

    const int tid  = threadIdx.x;
    const int lane = tid & 31;
    const int w    = tid >> 5;
    const int g    = lane >> 2;
    const int t    = lane & 3;
    const int b    = id >> 6;
    const int f0   = (id & 63) * 2;
    const int sub  = w >> 2;
    const int row0 = (w & 3) * 16;
    const int rrA  = row0 + g, rrB = row0 + g + 8;
    const int f    = f0 + sub;

    uint32_t* KTHs = KTH + sub * 1280;
    uint32_t* KTLs = KTL + sub * 1280;
    uint32_t* VTHs = VTH + sub * 1152;
    uint32_t* VTLs = VTL + sub * 1152;

    const uint32_t sb  = (uint32_t)__cvta_generic_to_shared(smw);
    const uint32_t XHb = sb + (uint32_t)(sub * 2304) * 4u;   // XL delta = 18432 B
    const uint32_t WCb = sb + 9216u * 4u;                    // lo delta = 13824 B
    const uint32_t WOb = sb + 16128u * 4u;                   // lo delta = 5120 B
    const uint32_t KTb = sb + (18688u + (uint32_t)(sub * 1280)) * 4u;  // lo delta 10240 B
    const uint32_t VTb = sb + (23808u + (uint32_t)(sub * 1152)) * 4u;  // lo delta 9216 B

    // Stage x slices + WC(0)
    for (int i = tid; i < 2 * 64 * 32; i += 256) {
        int s = i >> 11, rem = i & 2047, row = rem >> 5, dp = rem & 31;
        const float* xp = x + ((size_t)(b * TT + row) * FF + (f0 + s)) * DD;
        float2 v = *(const float2*)(xp + 2 * dp);
        split_pk(v.x, v.y, XH[s * 2304 + row * 36 + dp], XL[s * 2304 + row * 36 + dp]);
    }
    {
        uint4* dstv = (uint4*)(smw + 9216);
        for (int i = tid; i < 1728; i += 256) dstv[i] = wsrc[i];
    }

    float oacc[8][4];
#pragma unroll
    for (int j = 0; j < 8; j++)
#pragma unroll
        for (int i = 0; i < 4; i++) oacc[j][i] = 0.f;

    for (int h = 0; h < HH; h++) {
        __syncthreads();
        // Stage WO(h)
        {
            const uint4* srcv = wsrc + (size_t)h * 2368 + 1728;
            uint4* dstv = (uint4*)(smw + 16128);
            for (int i = tid; i < 640; i += 256) dstv[i] = srcv[i];
        }

        // --- GEMM1 ---
        float c12[12][4];
#pragma unroll
        for (int j = 0; j < 12; j++)
#pragma unroll
            for (int i = 0; i < 4; i++) c12[j][i] = 0.f;
        for (int kk = 0; kk < 4; kk++) {
            uint32_t ah[4], al[4];
            ldA4(XHb, 36, row0 * 36 + kk * 8, lane, ah);
            ldA4(XHb + 18432u, 36, row0 * 36 + kk * 8, lane, al);
#pragma unroll
            for (int j = 0; j < 12; j++) {
                uint32_t bh2[2], bl2[2];
                ldB4(WCb, 13824u, 36, j * 8 * 36 + kk * 8, lane, bh2, bl2);
                mma3(c12[j], ah, al, bh2, bl2);
            }
        }
        uint32_t QAh[2][4], QAl[2][4];
#pragma unroll
        for (int j = 0; j < 4; j++) {
            int cc = j * 8 + 2 * t;
            float b0 = bq_g[h * 32 + cc], b1 = bq_g[h * 32 + cc + 1];
            float v0 = (c12[j][0] + b0) * QSCALE, v1 = (c12[j][1] + b1) * QSCALE;
            float v2 = (c12[j][2] + b0) * QSCALE, v3 = (c12[j][3] + b1) * QSCALE;
            int kc = j >> 1, e = j & 1;
            split_pk(v0, v1, QAh[kc][2 * e],     QAl[kc][2 * e]);
            split_pk(v2, v3, QAh[kc][2 * e + 1], QAl[kc][2 * e + 1]);
        }
#pragma unroll
        for (int j = 4; j < 8; j++) {
            int cc = (j - 4) * 8 + 2 * t;
            float b0 = bk_g[h * 32 + cc], b1 = bk_g[h * 32 + cc + 1];
            int kp = cc >> 1;
            split_pk(c12[j][0] + b0, c12[j][1] + b1, KTHs[rrA * 20 + kp], KTLs[rrA * 20 + kp]);
            split_pk(c12[j][2] + b0, c12[j][3] + b1, KTHs[rrB * 20 + kp], KTLs[rrB * 20 + kp]);
        }
        {
            __nv_bfloat16* vh = reinterpret_cast<__nv_bfloat16*>(VTHs);
            __nv_bfloat16* vl = reinterpret_cast<__nv_bfloat16*>(VTLs);
#pragma unroll
            for (int j = 8; j < 12; j++) {
                int vk = (j - 8) * 8 + 2 * t;
                float b0 = bv_g[h * 32 + vk], b1 = bv_g[h * 32 + vk + 1];
                float vv[4] = {c12[j][0] + b0, c12[j][1] + b1, c12[j][2] + b0, c12[j][3] + b1};
                int   cl[4] = {vk, vk + 1, vk, vk + 1};
                int   rw[4] = {rrA, rrA, rrB, rrB};
#pragma unroll
                for (int q2 = 0; q2 < 4; q2++) {
                    __nv_bfloat16 hb = __float2bfloat16(vv[q2]);
                    float lf = vv[q2] - __bfloat162float(hb);
                    vh[cl[q2] * 72 + rw[q2]] = hb;
                    vl[cl[q2] * 72 + rw[q2]] = __float2bfloat16(lf);
                }
            }
        }
        __syncthreads();   // CTA-wide: K/V + WO visible, WC reads complete

        // Prefetch WC(h+1) overlapped with S/PV/outproj below.
        if (h < 3) {
            const uint4* srcv = wsrc + (size_t)(h + 1) * 2368;
            uint4* dstv = (uint4*)(smw + 9216);
            for (int i = tid; i < 1728; i += 256) dstv[i] = srcv[i];
        }

        // --- S = Q K^T over 64 cols, dual accumulators ---
        float cS[8][4];
        {
            float cC[8][4];
#pragma unroll
            for (int j = 0; j < 8; j++)
#pragma unroll
                for (int i = 0; i < 4; i++) { cS[j][i] = 0.f; cC[j][i] = 0.f; }
#pragma unroll
            for (int kk = 0; kk < 2; kk++) {
#pragma unroll
                for (int j = 0; j < 8; j++) {
                    uint32_t bh2[2], bl2[2];
                    ldB4(KTb, 10240u, 20, j * 8 * 20 + kk * 8, lane, bh2, bl2);
                    mma3d(cS[j], cC[j], QAh[kk], QAl[kk], bh2, bl2);
                }
            }
#pragma unroll
            for (int j = 0; j < 8; j++)
#pragma unroll
                for (int i = 0; i < 4; i++) cS[j][i] += cC[j][i];
        }
        float mA = cS[0][0], mB = cS[0][2];
#pragma unroll
        for (int j = 0; j < 8; j++) {
            mA = fmaxf(mA, fmaxf(cS[j][0], cS[j][1]));
            mB = fmaxf(mB, fmaxf(cS[j][2], cS[j][3]));
        }
        mA = fmaxf(mA, __shfl_xor_sync(0xffffffff, mA, 1));
        mA = fmaxf(mA, __shfl_xor_sync(0xffffffff, mA, 2));
        mB = fmaxf(mB, __shfl_xor_sync(0xffffffff, mB, 1));
        mB = fmaxf(mB, __shfl_xor_sync(0xffffffff, mB, 2));
        float sA = 0.f, sB = 0.f;
#pragma unroll
        for (int j = 0; j < 8; j++) {
            cS[j][0] = ex2f(cS[j][0] - mA); sA += cS[j][0];
            cS[j][1] = ex2f(cS[j][1] - mA); sA += cS[j][1];
            cS[j][2] = ex2f(cS[j][2] - mB); sB += cS[j][2];
            cS[j][3] = ex2f(cS[j][3] - mB); sB += cS[j][3];
        }
        sA += __shfl_xor_sync(0xffffffff, sA, 1);
        sA += __shfl_xor_sync(0xffffffff, sA, 2);
        sB += __shfl_xor_sync(0xffffffff, sB, 1);
        sB += __shfl_xor_sync(0xffffffff, sB, 2);
        float invA = __fdividef(1.f, sA), invB = __fdividef(1.f, sB);

        // P -> regs (A-frags for PV)
        uint32_t PAh[4][4], PAl[4][4];
#pragma unroll
        for (int kc = 0; kc < 4; kc++) {
            int j0 = 2 * kc;
            split_pk(cS[j0][0] * invA,     cS[j0][1] * invA,     PAh[kc][0], PAl[kc][0]);
            split_pk(cS[j0][2] * invB,     cS[j0][3] * invB,     PAh[kc][1], PAl[kc][1]);
            split_pk(cS[j0 + 1][0] * invA, cS[j0 + 1][1] * invA, PAh[kc][2], PAl[kc][2]);
            split_pk(cS[j0 + 1][2] * invB, cS[j0 + 1][3] * invB, PAh[kc][3], PAl[kc][3]);
        }

        // --- PV: dual accumulators ---
        float cP[4][4];
        {
            float cC2[4][4];
#pragma unroll
            for (int j = 0; j < 4; j++)
#pragma unroll
                for (int i = 0; i < 4; i++) { cP[j][i] = 0.f; cC2[j][i] = 0.f; }
#pragma unroll
            for (int kk = 0; kk < 4; kk++) {
#pragma unroll
                for (int j = 0; j < 4; j++) {
                    uint32_t bh2[2], bl2[2];
                    ldB4(VTb, 9216u, 36, j * 8 * 36 + kk * 8, lane, bh2, bl2);
                    mma3d(cP[j], cC2[j], PAh[kk], PAl[kk], bh2, bl2);
                }
            }
#pragma unroll
            for (int j = 0; j < 4; j++)
#pragma unroll
                for (int i = 0; i < 4; i++) cP[j][i] += cC2[j][i];
        }

        // O -> regs, outproj accumulate
        uint32_t OAh[2][4], OAl[2][4];
#pragma unroll
        for (int j = 0; j < 4; j++) {
            int kc = j >> 1, e = j & 1;
            split_pk(cP[j][0], cP[j][1], OAh[kc][2 * e],     OAl[kc][2 * e]);
            split_pk(cP[j][2], cP[j][3], OAh[kc][2 * e + 1], OAl[kc][2 * e + 1]);
        }
#pragma unroll
        for (int kk = 0; kk < 2; kk++) {
#pragma unroll
            for (int j = 0; j < 8; j++) {
                uint32_t bh2[2], bl2[2];
                ldB4(WOb, 5120u, 20, j * 8 * 20 + kk * 8, lane, bh2, bl2);
                mma3(oacc[j], OAh[kk], OAl[kk], bh2, bl2);
            }
        }
    }

    // Deposit into out. rows = t, cols = d
#pragma unroll
    for (int j = 0; j < 8; j++) {
        int d0 = j * 8 + 2 * t;
        float bo0 = bo_g[d0], bo1 = bo_g[d0 + 1];
        size_t base0 = ((size_t)(b * TT + rrA) * FF + f) * DD;
        size_t base1 = ((size_t)(b * TT + rrB) * FF + f) * DD;
        atomicAdd(out + base0 + d0,     oacc[j][0] + bo0);
        atomicAdd(out + base0 + d0 + 1, oacc[j][1] + bo1);
        atomicAdd(out + base1 + d0,     oacc[j][2] + bo0);
        atomicAdd(out + base1 + d0 + 1, oacc[j][3] + bo1);
    }
}

// ---------------------------------------------------------------------------
// Fused kernel: even blocks -> temporal, odd blocks -> feature (interleaved).
// ---------------------------------------------------------------------------
__global__ __launch_bounds__(256, 2) void fused_kernel(
    const float* __restrict__ x,
    const float* __restrict__ tqb, const float* __restrict__ tkb,
    const float* __restrict__ tvb, const float* __restrict__ tob,
    const float* __restrict__ fqb, const float* __restrict__ fkb,
    const float* __restrict__ fvb, const float* __restrict__ fob,
    float* __restrict__ out)
{
    extern __shared__ uint32_t smw[];
    int id = blockIdx.x >> 1;
    if ((blockIdx.x & 1) == 0) {
        temporal_body(smw, id, x, &g_w[0][0][0], tqb, tkb, tvb, tob, out);
    } else {
        feature_body(smw, id, x, &g_w[1][0][0], fqb, fkb, fvb, fob, out);
    }
}

extern "C" void kernel_launch(void* const* d_in, const int* in_sizes, int n_in,
                              void* d_out, int out_size)
{
    const float* x = (const float*)d_in[0];
    const float *tqw, *tqb, *tkw, *tkb, *tvw, *tvb, *tow, *tob;
    const float *fqw, *fqb, *fkw, *fkb, *fvw, *fvb, *fow, *fob;

    if (in_sizes[8] == 64) {  // reference-signature order
        tqw = (const float*)d_in[1];  tqb = (const float*)d_in[2];
        tkw = (const float*)d_in[3];  tkb = (const float*)d_in[4];
        tvw = (const float*)d_in[5];  tvb = (const float*)d_in[6];
        tow = (const float*)d_in[7];  tob = (const float*)d_in[8];
        fqw = (const float*)d_in[9];  fqb = (const float*)d_in[10];
        fkw = (const float*)d_in[11]; fkb = (const float*)d_in[12];
        fvw = (const float*)d_in[13]; fvb = (const float*)d_in[14];
        fow = (const float*)d_in[15]; fob = (const float*)d_in[16];
    } else {                  // setup_inputs dict order
        tqw = (const float*)d_in[1];  tqb = (const float*)d_in[2];
        tkw = (const float*)d_in[3];  tkb = (const float*)d_in[4];
        tvw = (const float*)d_in[5];  tvb = (const float*)d_in[6];
        fqw = (const float*)d_in[7];  fqb = (const float*)d_in[8];
        fkw = (const float*)d_in[9];  fkb = (const float*)d_in[10];
        fvw = (const float*)d_in[11]; fvb = (const float*)d_in[12];
        tow = (const float*)d_in[13]; tob = (const float*)d_in[14];
        fow = (const float*)d_in[15]; fob = (const float*)d_in[16];
    }

    const int SMEM = 28416 * 4;     // 113664 B -> 2 CTA/SM
    cudaFuncSetAttribute(fused_kernel,
                         cudaFuncAttributeMaxDynamicSharedMemorySize, SMEM);

    cudaMemsetAsync(d_out, 0, (size_t)out_size * sizeof(float), 0);
    prep_kernel<<<8, 256>>>(tqw, tkw, tvw, tow, fqw, fkw, fvw, fow);
    fused_kernel<<<4096, 256, SMEM>>>(
        x, tqb, tkb, tvb, tob, fqb, fkb, fvb, fob, (float*)d_out);
}

// round 16
// speedup vs baseline: 1.0253x; 1.0253x over previous
#include <cuda_runtime.h>
#include <cuda_bf16.h>
#include <math.h>
#include <stdint.h>

#define BB 32
#define TT 64
#define FF 128
#define DD 64
#define HH 4
#define KK 32
// (1/sqrt(32)) * log2(e): softmax in log2 domain with ex2
#define QSCALE (0.17677669529663687f * 1.4426950408889634f)

// Pre-split weight buffer: [side][head][9472 words as uint4]
// per head: [0,3456) WCH | [3456,6912) WCL | [6912,8192) WOH | [8192,9472) WOL
// as uint4: WC = [0,1728), WO = [1728,2368)
__device__ uint4 g_w[2][4][2368];

__device__ __forceinline__ float ex2f(float x) {
    float y;
    asm("ex2.approx.ftz.f32 %0, %1;" : "=f"(y) : "f"(x));
    return y;
}

// Split two fp32 into packed bf16 hi-pair and lo-pair (v ~= hi + lo, err ~2^-18).
__device__ __forceinline__ void split_pk(float v0, float v1, uint32_t& hi, uint32_t& lo) {
    uint32_t h;
    asm("cvt.rn.bf16x2.f32 %0, %1, %2;" : "=r"(h) : "f"(v1), "f"(v0));
    float h0f = __uint_as_float(h << 16);
    float h1f = __uint_as_float(h & 0xffff0000u);
    float l0 = v0 - h0f;
    float l1 = v1 - h1f;
    uint32_t l;
    asm("cvt.rn.bf16x2.f32 %0, %1, %2;" : "=r"(l) : "f"(l1), "f"(l0));
    hi = h;
    lo = l;
}

// m16n8k16 bf16 mma, C += A*B (fp32 accum).
__device__ __forceinline__ void mmabf(float* c, const uint32_t* a, const uint32_t* b) {
    asm volatile(
        "mma.sync.aligned.m16n8k16.row.col.f32.bf16.bf16.f32 "
        "{%0,%1,%2,%3}, {%4,%5,%6,%7}, {%8,%9}, {%0,%1,%2,%3};"
        : "+f"(c[0]), "+f"(c[1]), "+f"(c[2]), "+f"(c[3])
        : "r"(a[0]), "r"(a[1]), "r"(a[2]), "r"(a[3]), "r"(b[0]), "r"(b[1]));
}
// 3-term compensated product: C += (Ah+Al)*(Bh+Bl), dropping Al*Bl.
__device__ __forceinline__ void mma3(float* c, const uint32_t* ah, const uint32_t* al,
                                     const uint32_t* bh, const uint32_t* bl) {
    mmabf(c, al, bh);
    mmabf(c, ah, bl);
    mmabf(c, ah, bh);
}

// ldmatrix.x4
__device__ __forceinline__ void ldsm4(uint32_t addr, uint32_t* r) {
    asm volatile("ldmatrix.sync.aligned.m8n8.x4.shared.b16 {%0,%1,%2,%3}, [%4];"
        : "=r"(r[0]), "=r"(r[1]), "=r"(r[2]), "=r"(r[3])
        : "r"(addr));
}

// B hi+lo fragment pair via one LDSM.x4.
__device__ __forceinline__ void ldB4(uint32_t base, uint32_t lodelta, int W, int off_w,
                                     int lane, uint32_t* bh, uint32_t* bl) {
    uint32_t a = base + (uint32_t)off_w * 4u
               + (uint32_t)(lane & 7) * (uint32_t)(W * 4)
               + (uint32_t)((lane >> 3) & 1) * 16u
               + (uint32_t)((lane >> 4) & 1) * lodelta;
    uint32_t r[4];
    ldsm4(a, r);
    bh[0] = r[0]; bh[1] = r[1]; bl[0] = r[2]; bl[1] = r[3];
}

// A fragment via one LDSM.x4.
__device__ __forceinline__ void ldA4(uint32_t base, int W, int off_w, int lane, uint32_t* a) {
    uint32_t ad = base + (uint32_t)off_w * 4u
                + (uint32_t)((lane & 7) + ((lane >> 3) & 1) * 8) * (uint32_t)(W * 4)
                + (uint32_t)((lane >> 4) & 1) * 16u;
    ldsm4(ad, a);
}

// Feature S-chunk mma: 32 cols of S (4 j-tiles x 2 ksteps x mma3).
__device__ __forceinline__ void sfeat_chunk(
    uint32_t KTb, int c, int lane,
    const uint32_t QAh[2][4], const uint32_t QAl[2][4], float cS[4][4])
{
#pragma unroll
    for (int j = 0; j < 4; j++)
#pragma unroll
        for (int i = 0; i < 4; i++) cS[j][i] = 0.f;
#pragma unroll
    for (int kk = 0; kk < 2; kk++) {
#pragma unroll
        for (int j = 0; j < 4; j++) {
            uint32_t bh2[2], bl2[2];
            ldB4(KTb, 10240u, 20, (c * 4 + j) * 8 * 20 + kk * 8, lane, bh2, bl2);
            mma3(cS[j], QAh[kk], QAl[kk], bh2, bl2);
        }
    }
}

// ---------------------------------------------------------------------------
// Prep kernel: split all weights once into g_w (smem-staging layout).
// ---------------------------------------------------------------------------
__global__ void prep_kernel(
    const float* __restrict__ tqw, const float* __restrict__ tkw,
    const float* __restrict__ tvw, const float* __restrict__ tow,
    const float* __restrict__ fqw, const float* __restrict__ fkw,
    const float* __restrict__ fvw, const float* __restrict__ fow)
{
    int side = blockIdx.x >> 2, h = blockIdx.x & 3;
    const float* wq = side ? fqw : tqw;
    const float* wk = side ? fkw : tkw;
    const float* wv = side ? fvw : tvw;
    const float* wo = side ? fow : tow;
    uint32_t* dstw = (uint32_t*)&g_w[side][h][0];
    int tid = threadIdx.x;
    for (int i = tid; i < 96 * 32; i += 256) {
        int n = i % 96, dp = i / 96;
        const float* src = (n < 32) ? wq : (n < 64) ? wk : wv;
        int nn = n & 31;
        float v0 = src[(2 * dp) * 128 + h * 32 + nn];
        float v1 = src[(2 * dp + 1) * 128 + h * 32 + nn];
        split_pk(v0, v1, dstw[n * 36 + dp], dstw[3456 + n * 36 + dp]);
    }
    for (int i = tid; i < 64 * 16; i += 256) {
        int d = i & 63, kp = i >> 6;
        float v0 = wo[h * 2048 + (2 * kp) * 64 + d];
        float v1 = wo[h * 2048 + (2 * kp + 1) * 64 + d];
        split_pk(v0, v1, dstw[6912 + d * 20 + kp], dstw[8192 + d * 20 + kp]);
    }
}

// ---------------------------------------------------------------------------
// Feature body: id -> (b, t). 128 rows, 8 warps x 16 rows. atomicAdd into out.
// WC(h+1) prefetched after the KV barrier, overlapping S/PV tensor work.
// ---------------------------------------------------------------------------
__device__ __forceinline__ void feature_body(
    uint32_t* smw, int id,
    const float* __restrict__ x,
    const uint4* __restrict__ wsrc,
    const float* __restrict__ bq_g, const float* __restrict__ bk_g,
    const float* __restrict__ bv_g, const float* __restrict__ bo_g,
    float* __restrict__ out)
{
    uint32_t* XH  = smw;            // 128 x 36
    uint32_t* XL  = smw + 4608;
    uint32_t* KTH = smw + 18688;    // 128 x 20
    uint32_t* KTL = smw + 21248;
    uint32_t* VTH = smw + 23808;    // 32 x 68
    uint32_t* VTL = smw + 25984;    // -> 28160

    const uint32_t sb = (uint32_t)__cvta_generic_to_shared(smw);
    const uint32_t XHb = sb;                    // XL delta = 18432 B
    const uint32_t WCb = sb + 9216u * 4u;       // lo delta = 13824 B
    const uint32_t WOb = sb + 16128u * 4u;      // lo delta = 5120 B
    const uint32_t KTb = sb + 18688u * 4u;      // lo delta = 10240 B
    const uint32_t VTb = sb + 23808u * 4u;      // lo delta = 8704 B

    const int tid  = threadIdx.x;
    const int lane = tid & 31;
    const int w    = tid >> 5;
    const int g    = lane >> 2;
    const int t    = lane & 3;
    const int b    = id >> 6;
    const int tt   = id & 63;
    const int row0 = w * 16;
    const int rrA  = row0 + g, rrB = row0 + g + 8;

    // Stage x slice + WC(0)
    {
        const float* xp = x + (size_t)(b * TT + tt) * (FF * DD);
        for (int i = tid; i < FF * 32; i += 256) {
            int row = i >> 5, dp = i & 31;
            float2 v = *(const float2*)(xp + row * 64 + 2 * dp);
            split_pk(v.x, v.y, XH[row * 36 + dp], XL[row * 36 + dp]);
        }
        uint4* dstv = (uint4*)(smw + 9216);
        for (int i = tid; i < 1728; i += 256) dstv[i] = wsrc[i];
    }

    float oacc[8][4];
#pragma unroll
    for (int j = 0; j < 8; j++)
#pragma unroll
        for (int i = 0; i < 4; i++) oacc[j][i] = 0.f;

    for (int h = 0; h < HH; h++) {
        __syncthreads();   // WC(h)/x writes visible; prior head's WO reads done
        // Stage WO(h): LDG latency overlaps GEMM1 (WO read only after KV sync)
        {
            const uint4* srcv = wsrc + (size_t)h * 2368 + 1728;
            uint4* dstv = (uint4*)(smw + 16128);
            for (int i = tid; i < 640; i += 256) dstv[i] = srcv[i];
        }

        // --- GEMM1: [16 rows] x [k=64] x [n=96] ---
        float c12[12][4];
#pragma unroll
        for (int j = 0; j < 12; j++)
#pragma unroll
            for (int i = 0; i < 4; i++) c12[j][i] = 0.f;
        for (int kk = 0; kk < 4; kk++) {
            uint32_t ah[4], al[4];
            ldA4(XHb, 36, row0 * 36 + kk * 8, lane, ah);
            ldA4(XHb + 18432u, 36, row0 * 36 + kk * 8, lane, al);
#pragma unroll
            for (int j = 0; j < 12; j++) {
                uint32_t bh2[2], bl2[2];
                ldB4(WCb, 13824u, 36, j * 8 * 36 + kk * 8, lane, bh2, bl2);
                mma3(c12[j], ah, al, bh2, bl2);
            }
        }
        // Epilogue: Q -> regs, K -> smem, V -> smem transposed
        uint32_t QAh[2][4], QAl[2][4];
#pragma unroll
        for (int j = 0; j < 4; j++) {
            int cc = j * 8 + 2 * t;
            float b0 = bq_g[h * 32 + cc], b1 = bq_g[h * 32 + cc + 1];
            float v0 = (c12[j][0] + b0) * QSCALE, v1 = (c12[j][1] + b1) * QSCALE;
            float v2 = (c12[j][2] + b0) * QSCALE, v3 = (c12[j][3] + b1) * QSCALE;
            int kc = j >> 1, e = j & 1;
            split_pk(v0, v1, QAh[kc][2 * e],     QAl[kc][2 * e]);
            split_pk(v2, v3, QAh[kc][2 * e + 1], QAl[kc][2 * e + 1]);
        }
#pragma unroll
        for (int j = 4; j < 8; j++) {
            int cc = (j - 4) * 8 + 2 * t;
            float b0 = bk_g[h * 32 + cc], b1 = bk_g[h * 32 + cc + 1];
            int kp = cc >> 1;
            split_pk(c12[j][0] + b0, c12[j][1] + b1, KTH[rrA * 20 + kp], KTL[rrA * 20 + kp]);
            split_pk(c12[j][2] + b0, c12[j][3] + b1, KTH[rrB * 20 + kp], KTL[rrB * 20 + kp]);
        }
        {
            __nv_bfloat16* vh = reinterpret_cast<__nv_bfloat16*>(VTH);
            __nv_bfloat16* vl = reinterpret_cast<__nv_bfloat16*>(VTL);
#pragma unroll
            for (int j = 8; j < 12; j++) {
                int vk = (j - 8) * 8 + 2 * t;
                float b0 = bv_g[h * 32 + vk], b1 = bv_g[h * 32 + vk + 1];
                float vv[4] = {c12[j][0] + b0, c12[j][1] + b1, c12[j][2] + b0, c12[j][3] + b1};
                int   cl[4] = {vk, vk + 1, vk, vk + 1};
                int   rw[4] = {rrA, rrA, rrB, rrB};
#pragma unroll
                for (int q2 = 0; q2 < 4; q2++) {
                    __nv_bfloat16 hb = __float2bfloat16(vv[q2]);
                    float lf = vv[q2] - __bfloat162float(hb);
                    vh[cl[q2] * 136 + rw[q2]] = hb;
                    vl[cl[q2] * 136 + rw[q2]] = __float2bfloat16(lf);
                }
            }
        }
        __syncthreads();   // K/V + WO visible; GEMM1's WC reads complete

        // Prefetch WC(h+1): LDG/STS overlap the S/PV/outproj tensor work below.
        if (h < 3) {
            const uint4* srcv = wsrc + (size_t)(h + 1) * 2368;
            uint4* dstv = (uint4*)(smw + 9216);
            for (int i = tid; i < 1728; i += 256) dstv[i] = srcv[i];
        }

        // --- S = Q K^T, online softmax, fused PV; pipelined over 4 chunks ---
        float cP[4][4];
#pragma unroll
        for (int j = 0; j < 4; j++)
#pragma unroll
            for (int i = 0; i < 4; i++) cP[j][i] = 0.f;
        float mrA, mrB, sA, sB;
        float cSb[2][4][4];

        sfeat_chunk(KTb, 0, lane, QAh, QAl, cSb[0]);
#pragma unroll
        for (int c = 0; c < 4; c++) {
            float (*cS)[4] = cSb[c & 1];
            if (c < 3) sfeat_chunk(KTb, c + 1, lane, QAh, QAl, cSb[(c + 1) & 1]);

            float mA = cS[0][0], mB = cS[0][2];
#pragma unroll
            for (int j = 0; j < 4; j++) {
                mA = fmaxf(mA, fmaxf(cS[j][0], cS[j][1]));
                mB = fmaxf(mB, fmaxf(cS[j][2], cS[j][3]));
            }
            mA = fmaxf(mA, __shfl_xor_sync(0xffffffff, mA, 1));
            mA = fmaxf(mA, __shfl_xor_sync(0xffffffff, mA, 2));
            mB = fmaxf(mB, __shfl_xor_sync(0xffffffff, mB, 1));
            mB = fmaxf(mB, __shfl_xor_sync(0xffffffff, mB, 2));
            float nmA, nmB, chA = 0.f, chB = 0.f;
            if (c == 0) {
                nmA = mA; nmB = mB;
#pragma unroll
                for (int j = 0; j < 4; j++) {
                    cS[j][0] = ex2f(cS[j][0] - nmA); chA += cS[j][0];
                    cS[j][1] = ex2f(cS[j][1] - nmA); chA += cS[j][1];
                    cS[j][2] = ex2f(cS[j][2] - nmB); chB += cS[j][2];
                    cS[j][3] = ex2f(cS[j][3] - nmB); chB += cS[j][3];
                }
                sA = chA; sB = chB;
            } else {
                nmA = fmaxf(mrA, mA); nmB = fmaxf(mrB, mB);
                float scA = ex2f(mrA - nmA), scB = ex2f(mrB - nmB);
#pragma unroll
                for (int j = 0; j < 4; j++) {
                    cS[j][0] = ex2f(cS[j][0] - nmA); chA += cS[j][0];
                    cS[j][1] = ex2f(cS[j][1] - nmA); chA += cS[j][1];
                    cS[j][2] = ex2f(cS[j][2] - nmB); chB += cS[j][2];
                    cS[j][3] = ex2f(cS[j][3] - nmB); chB += cS[j][3];
                }
                sA = sA * scA + chA;
                sB = sB * scB + chB;
#pragma unroll
                for (int j = 0; j < 4; j++) {
                    cP[j][0] *= scA; cP[j][1] *= scA;
                    cP[j][2] *= scB; cP[j][3] *= scB;
                }
            }
            uint32_t ph[2][4], pl[2][4];
#pragma unroll
            for (int k0e = 0; k0e < 2; k0e++) {
                int j0 = 2 * k0e;
                split_pk(cS[j0][0],     cS[j0][1],     ph[k0e][0], pl[k0e][0]);
                split_pk(cS[j0][2],     cS[j0][3],     ph[k0e][1], pl[k0e][1]);
                split_pk(cS[j0 + 1][0], cS[j0 + 1][1], ph[k0e][2], pl[k0e][2]);
                split_pk(cS[j0 + 1][2], cS[j0 + 1][3], ph[k0e][3], pl[k0e][3]);
            }
#pragma unroll
            for (int k0e = 0; k0e < 2; k0e++) {
                int kkv = 2 * c + k0e;
#pragma unroll
                for (int j = 0; j < 4; j++) {
                    uint32_t bh2[2], bl2[2];
                    ldB4(VTb, 8704u, 68, j * 8 * 68 + kkv * 8, lane, bh2, bl2);
                    mma3(cP[j], ph[k0e], pl[k0e], bh2, bl2);
                }
            }
            mrA = nmA; mrB = nmB;
        }
        sA += __shfl_xor_sync(0xffffffff, sA, 1);
        sA += __shfl_xor_sync(0xffffffff, sA, 2);
        sB += __shfl_xor_sync(0xffffffff, sB, 1);
        sB += __shfl_xor_sync(0xffffffff, sB, 2);
        float invA = __fdividef(1.f, sA), invB = __fdividef(1.f, sB);
#pragma unroll
        for (int j = 0; j < 4; j++) {
            cP[j][0] *= invA; cP[j][1] *= invA;
            cP[j][2] *= invB; cP[j][3] *= invB;
        }

        // O -> regs, outproj accumulate
        uint32_t OAh[2][4], OAl[2][4];
#pragma unroll
        for (int j = 0; j < 4; j++) {
            int kc = j >> 1, e = j & 1;
            split_pk(cP[j][0], cP[j][1], OAh[kc][2 * e],     OAl[kc][2 * e]);
            split_pk(cP[j][2], cP[j][3], OAh[kc][2 * e + 1], OAl[kc][2 * e + 1]);
        }
#pragma unroll
        for (int kk = 0; kk < 2; kk++) {
#pragma unroll
            for (int j = 0; j < 8; j++) {
                uint32_t bh2[2], bl2[2];
                ldB4(WOb, 5120u, 20, j * 8 * 20 + kk * 8, lane, bh2, bl2);
                mma3(oacc[j], OAh[kk], OAl[kk], bh2, bl2);
            }
        }
    }

    // Deposit into out (zero-initialized by memset). rows = f, cols = d
#pragma unroll
    for (int j = 0; j < 8; j++) {
        int d0 = j * 8 + 2 * t;
        float bo0 = bo_g[d0], bo1 = bo_g[d0 + 1];
        size_t base0 = ((size_t)(b * TT + tt) * FF + rrA) * DD;
        size_t base1 = ((size_t)(b * TT + tt) * FF + rrB) * DD;
        atomicAdd(out + base0 + d0,     oacc[j][0] + bo0);
        atomicAdd(out + base0 + d0 + 1, oacc[j][1] + bo1);
        atomicAdd(out + base1 + d0,     oacc[j][2] + bo0);
        atomicAdd(out + base1 + d0 + 1, oacc[j][3] + bo1);
    }
}

// ---------------------------------------------------------------------------
// Temporal body: id -> (b, f-pair). 2 sub-blocks x 64 rows (T). atomicAdd out.
// KV barrier is CTA-wide (orders WC prefetch writes vs other sub's WC reads).
// ---------------------------------------------------------------------------
__device__ __forceinline__ void temporal_body(
    uint32_t* smw, int id,
    const float* __restrict__ x,
    const uint4* __restrict__ wsrc,
    const float* __restrict__ bq_g, const float* __restrict__ bk_g,
    const float* __restrict__ bv_g, const float* __restrict__ bo_g,
    float* __restrict__ out)
{
    uint32_t* XH  = smw;            // 2 x (64 x 36)
    uint32_t* XL  = smw + 4608;
    uint32_t* KTH = smw + 18688;    // 2 x (64 x 20)
    uint32_t* KTL = smw + 21248;
    uint32_t* VTH = smw + 23808;    // 2 x (32 x 36)
    uint32_t* VTL = smw + 26112;    // -> 28416

    const int tid  = threadIdx.x;
    const int lane = tid & 31;
    const int w    = tid >> 5;
    const int g    = lane >> 2;
    const int t    = lane & 3;
    const int b    = id >> 6;
    const int f0   = (id & 63) * 2;
    const int sub  = w >> 2;
    const int row0 = (w & 3) * 16;
    const int rrA  = row0 + g, rrB = row0 + g + 8;
    const int f    = f0 + sub;

    uint32_t* KTHs = KTH + sub * 1280;
    uint32_t* KTLs = KTL + sub * 1280;
    uint32_t* VTHs = VTH + sub * 1152;
    uint32_t* VTLs = VTL + sub * 1152;

    const uint32_t sb  = (uint32_t)__cvta_generic_to_shared(smw);
    const uint32_t XHb = sb + (uint32_t)(sub * 2304) * 4u;   // XL delta = 18432 B
    const uint32_t WCb = sb + 9216u * 4u;                    // lo delta = 13824 B
    const uint32_t WOb = sb + 16128u * 4u;                   // lo delta = 5120 B
    const uint32_t KTb = sb + (18688u + (uint32_t)(sub * 1280)) * 4u;  // lo delta 10240 B
    const uint32_t VTb = sb + (23808u + (uint32_t)(sub * 1152)) * 4u;  // lo delta 9216 B

    // Stage x slices + WC(0)
    for (int i = tid; i < 2 * 64 * 32; i += 256) {
        int s = i >> 11, rem = i & 2047, row = rem >> 5, dp = rem & 31;
        const float* xp = x + ((size_t)(b * TT + row) * FF + (f0 + s)) * DD;
        float2 v = *(const float2*)(xp + 2 * dp);
        split_pk(v.x, v.y, XH[s * 2304 + row * 36 + dp], XL[s * 2304 + row * 36 + dp]);
    }
    {
        uint4* dstv = (uint4*)(smw + 9216);
        for (int i = tid; i < 1728; i += 256) dstv[i] = wsrc[i];
    }

    float oacc[8][4];
#pragma unroll
    for (int j = 0; j < 8; j++)
#pragma unroll
        for (int i = 0; i < 4; i++) oacc[j][i] = 0.f;

    for (int h = 0; h < HH; h++) {
        __syncthreads();
        // Stage WO(h)
        {
            const uint4* srcv = wsrc + (size_t)h * 2368 + 1728;
            uint4* dstv = (uint4*)(smw + 16128);
            for (int i = tid; i < 640; i += 256) dstv[i] = srcv[i];
        }

        // --- GEMM1 ---
        float c12[12][4];
#pragma unroll
        for (int j = 0; j < 12; j++)
#pragma unroll
            for (int i = 0; i < 4; i++) c12[j][i] = 0.f;
        for (int kk = 0; kk < 4; kk++) {
            uint32_t ah[4], al[4];
            ldA4(XHb, 36, row0 * 36 + kk * 8, lane, ah);
            ldA4(XHb + 18432u, 36, row0 * 36 + kk * 8, lane, al);
#pragma unroll
            for (int j = 0; j < 12; j++) {
                uint32_t bh2[2], bl2[2];
                ldB4(WCb, 13824u, 36, j * 8 * 36 + kk * 8, lane, bh2, bl2);
                mma3(c12[j], ah, al, bh2, bl2);
            }
        }
        uint32_t QAh[2][4], QAl[2][4];
#pragma unroll
        for (int j = 0; j < 4; j++) {
            int cc = j * 8 + 2 * t;
            float b0 = bq_g[h * 32 + cc], b1 = bq_g[h * 32 + cc + 1];
            float v0 = (c12[j][0] + b0) * QSCALE, v1 = (c12[j][1] + b1) * QSCALE;
            float v2 = (c12[j][2] + b0) * QSCALE, v3 = (c12[j][3] + b1) * QSCALE;
            int kc = j >> 1, e = j & 1;
            split_pk(v0, v1, QAh[kc][2 * e],     QAl[kc][2 * e]);
            split_pk(v2, v3, QAh[kc][2 * e + 1], QAl[kc][2 * e + 1]);
        }
#pragma unroll
        for (int j = 4; j < 8; j++) {
            int cc = (j - 4) * 8 + 2 * t;
            float b0 = bk_g[h * 32 + cc], b1 = bk_g[h * 32 + cc + 1];
            int kp = cc >> 1;
            split_pk(c12[j][0] + b0, c12[j][1] + b1, KTHs[rrA * 20 + kp], KTLs[rrA * 20 + kp]);
            split_pk(c12[j][2] + b0, c12[j][3] + b1, KTHs[rrB * 20 + kp], KTLs[rrB * 20 + kp]);
        }
        {
            __nv_bfloat16* vh = reinterpret_cast<__nv_bfloat16*>(VTHs);
            __nv_bfloat16* vl = reinterpret_cast<__nv_bfloat16*>(VTLs);
#pragma unroll
            for (int j = 8; j < 12; j++) {
                int vk = (j - 8) * 8 + 2 * t;
                float b0 = bv_g[h * 32 + vk], b1 = bv_g[h * 32 + vk + 1];
                float vv[4] = {c12[j][0] + b0, c12[j][1] + b1, c12[j][2] + b0, c12[j][3] + b1};
                int   cl[4] = {vk, vk + 1, vk, vk + 1};
                int   rw[4] = {rrA, rrA, rrB, rrB};
#pragma unroll
                for (int q2 = 0; q2 < 4; q2++) {
                    __nv_bfloat16 hb = __float2bfloat16(vv[q2]);
                    float lf = vv[q2] - __bfloat162float(hb);
                    vh[cl[q2] * 72 + rw[q2]] = hb;
                    vl[cl[q2] * 72 + rw[q2]] = __float2bfloat16(lf);
                }
            }
        }
        __syncthreads();   // CTA-wide: K/V + WO visible, WC reads complete

        // Prefetch WC(h+1) overlapped with S/PV/outproj below.
        if (h < 3) {
            const uint4* srcv = wsrc + (size_t)(h + 1) * 2368;
            uint4* dstv = (uint4*)(smw + 9216);
            for (int i = tid; i < 1728; i += 256) dstv[i] = srcv[i];
        }

        // --- S = Q K^T over 64 cols, full-row softmax ---
        float cS[8][4];
#pragma unroll
        for (int j = 0; j < 8; j++)
#pragma unroll
            for (int i = 0; i < 4; i++) cS[j][i] = 0.f;
#pragma unroll
        for (int kk = 0; kk < 2; kk++) {
#pragma unroll
            for (int j = 0; j < 8; j++) {
                uint32_t bh2[2], bl2[2];
                ldB4(KTb, 10240u, 20, j * 8 * 20 + kk * 8, lane, bh2, bl2);
                mma3(cS[j], QAh[kk], QAl[kk], bh2, bl2);
            }
        }
        float mA = cS[0][0], mB = cS[0][2];
#pragma unroll
        for (int j = 0; j < 8; j++) {
            mA = fmaxf(mA, fmaxf(cS[j][0], cS[j][1]));
            mB = fmaxf(mB, fmaxf(cS[j][2], cS[j][3]));
        }
        mA = fmaxf(mA, __shfl_xor_sync(0xffffffff, mA, 1));
        mA = fmaxf(mA, __shfl_xor_sync(0xffffffff, mA, 2));
        mB = fmaxf(mB, __shfl_xor_sync(0xffffffff, mB, 1));
        mB = fmaxf(mB, __shfl_xor_sync(0xffffffff, mB, 2));
        float sA = 0.f, sB = 0.f;
#pragma unroll
        for (int j = 0; j < 8; j++) {
            cS[j][0] = ex2f(cS[j][0] - mA); sA += cS[j][0];
            cS[j][1] = ex2f(cS[j][1] - mA); sA += cS[j][1];
            cS[j][2] = ex2f(cS[j][2] - mB); sB += cS[j][2];
            cS[j][3] = ex2f(cS[j][3] - mB); sB += cS[j][3];
        }
        sA += __shfl_xor_sync(0xffffffff, sA, 1);
        sA += __shfl_xor_sync(0xffffffff, sA, 2);
        sB += __shfl_xor_sync(0xffffffff, sB, 1);
        sB += __shfl_xor_sync(0xffffffff, sB, 2);
        float invA = __fdividef(1.f, sA), invB = __fdividef(1.f, sB);

        // P -> regs (A-frags for PV)
        uint32_t PAh[4][4], PAl[4][4];
#pragma unroll
        for (int kc = 0; kc < 4; kc++) {
            int j0 = 2 * kc;
            split_pk(cS[j0][0] * invA,     cS[j0][1] * invA,     PAh[kc][0], PAl[kc][0]);
            split_pk(cS[j0][2] * invB,     cS[j0][3] * invB,     PAh[kc][1], PAl[kc][1]);
            split_pk(cS[j0 + 1][0] * invA, cS[j0 + 1][1] * invA, PAh[kc][2], PAl[kc][2]);
            split_pk(cS[j0 + 1][2] * invB, cS[j0 + 1][3] * invB, PAh[kc][3], PAl[kc][3]);
        }

        // --- PV ---
        float cP[4][4];
#pragma unroll
        for (int j = 0; j < 4; j++)
#pragma unroll
            for (int i = 0; i < 4; i++) cP[j][i] = 0.f;
#pragma unroll
        for (int kk = 0; kk < 4; kk++) {
#pragma unroll
            for (int j = 0; j < 4; j++) {
                uint32_t bh2[2], bl2[2];
                ldB4(VTb, 9216u, 36, j * 8 * 36 + kk * 8, lane, bh2, bl2);
                mma3(cP[j], PAh[kk], PAl[kk], bh2, bl2);
            }
        }

        // O -> regs, outproj accumulate
        uint32_t OAh[2][4], OAl[2][4];
#pragma unroll
        for (int j = 0; j < 4; j++) {
            int kc = j >> 1, e = j & 1;
            split_pk(cP[j][0], cP[j][1], OAh[kc][2 * e],     OAl[kc][2 * e]);
            split_pk(cP[j][2], cP[j][3], OAh[kc][2 * e + 1], OAl[kc][2 * e + 1]);
        }
#pragma unroll
        for (int kk = 0; kk < 2; kk++) {
#pragma unroll
            for (int j = 0; j < 8; j++) {
                uint32_t bh2[2], bl2[2];
                ldB4(WOb, 5120u, 20, j * 8 * 20 + kk * 8, lane, bh2, bl2);
                mma3(oacc[j], OAh[kk], OAl[kk], bh2, bl2);
            }
        }
    }

    // Deposit into out. rows = t, cols = d
#pragma unroll
    for (int j = 0; j < 8; j++) {
        int d0 = j * 8 + 2 * t;
        float bo0 = bo_g[d0], bo1 = bo_g[d0 + 1];
        size_t base0 = ((size_t)(b * TT + rrA) * FF + f) * DD;
        size_t base1 = ((size_t)(b * TT + rrB) * FF + f) * DD;
        atomicAdd(out + base0 + d0,     oacc[j][0] + bo0);
        atomicAdd(out + base0 + d0 + 1, oacc[j][1] + bo1);
        atomicAdd(out + base1 + d0,     oacc[j][2] + bo0);
        atomicAdd(out + base1 + d0 + 1, oacc[j][3] + bo1);
    }
}

// ---------------------------------------------------------------------------
// Fused kernel: even blocks -> temporal, odd blocks -> feature (interleaved).
// ---------------------------------------------------------------------------
__global__ __launch_bounds__(256, 2) void fused_kernel(
    const float* __restrict__ x,
    const float* __restrict__ tqb, const float* __restrict__ tkb,
    const float* __restrict__ tvb, const float* __restrict__ tob,
    const float* __restrict__ fqb, const float* __restrict__ fkb,
    const float* __restrict__ fvb, const float* __restrict__ fob,
    float* __restrict__ out)
{
    extern __shared__ uint32_t smw[];
    int id = blockIdx.x >> 1;
    if ((blockIdx.x & 1) == 0) {
        temporal_body(smw, id, x, &g_w[0][0][0], tqb, tkb, tvb, tob, out);
    } else {
        feature_body(smw, id, x, &g_w[1][0][0], fqb, fkb, fvb, fob, out);
    }
}

extern "C" void kernel_launch(void* const* d_in, const int* in_sizes, int n_in,
                              void* d_out, int out_size)
{
    const float* x = (const float*)d_in[0];
    const float *tqw, *tqb, *tkw, *tkb, *tvw, *tvb, *tow, *tob;
    const float *fqw, *fqb, *fkw, *fkb, *fvw, *fvb, *fow, *fob;

    if (in_sizes[8] == 64) {  // reference-signature order
        tqw = (const float*)d_in[1];  tqb = (const float*)d_in[2];
        tkw = (const float*)d_in[3];  tkb = (const float*)d_in[4];
        tvw = (const float*)d_in[5];  tvb = (const float*)d_in[6];
        tow = (const float*)d_in[7];  tob = (const float*)d_in[8];
        fqw = (const float*)d_in[9];  fqb = (const float*)d_in[10];
        fkw = (const float*)d_in[11]; fkb = (const float*)d_in[12];
        fvw = (const float*)d_in[13]; fvb = (const float*)d_in[14];
        fow = (const float*)d_in[15]; fob = (const float*)d_in[16];
    } else {                  // setup_inputs dict order
        tqw = (const float*)d_in[1];  tqb = (const float*)d_in[2];
        tkw = (const float*)d_in[3];  tkb = (const float*)d_in[4];
        tvw = (const float*)d_in[5];  tvb = (const float*)d_in[6];
        fqw = (const float*)d_in[7];  fqb = (const float*)d_in[8];
        fkw = (const float*)d_in[9];  fkb = (const float*)d_in[10];
        fvw = (const float*)d_in[11]; fvb = (const float*)d_in[12];
        tow = (const float*)d_in[13]; tob = (const float*)d_in[14];
        fow = (const float*)d_in[15]; fob = (const float*)d_in[16];
    }

    const int SMEM = 28416 * 4;     // 113664 B -> 2 CTA/SM
    cudaFuncSetAttribute(fused_kernel,
                         cudaFuncAttributeMaxDynamicSharedMemorySize, SMEM);

    cudaMemsetAsync(d_out, 0, (size_t)out_size * sizeof(float), 0);
    prep_kernel<<<8, 256>>>(tqw, tkw, tvw, tow, fqw, fkw, fvw, fow);
    fused_kernel<<<4096, 256, SMEM>>>(
        x, tqb, tkb, tvb, tob, fqb, fkb, fvb, fob, (float*)d_out);
}

// round 17
// speedup vs baseline: 1.0896x; 1.0627x over previous
#include <cuda_runtime.h>
#include <cuda_bf16.h>
#include <math.h>
#include <stdint.h>

#define BB 32
#define TT 64
#define FF 128
#define DD 64
#define HH 4
#define KK 32
// (1/sqrt(32)) * log2(e): softmax in log2 domain with ex2
#define QSCALE (0.17677669529663687f * 1.4426950408889634f)

// Pre-split weight buffer: [side][head][9472 words as uint4]
// per head: [0,3456) WCH | [3456,6912) WCL | [6912,8192) WOH | [8192,9472) WOL
// as uint4: WC = [0,1728), WO = [1728,2368)
__device__ uint4 g_w[2][4][2368];

__device__ __forceinline__ float ex2f(float x) {
    float y;
    asm("ex2.approx.ftz.f32 %0, %1;" : "=f"(y) : "f"(x));
    return y;
}

// Async 16B gmem->smem copy (no destination register; tracked by groups).
__device__ __forceinline__ void cp_async16(uint32_t smem_addr, const void* gptr) {
    asm volatile("cp.async.cg.shared.global [%0], [%1], 16;"
                 :: "r"(smem_addr), "l"(gptr) : "memory");
}
__device__ __forceinline__ void cp_commit() {
    asm volatile("cp.async.commit_group;" ::: "memory");
}
__device__ __forceinline__ void cp_wait0() {
    asm volatile("cp.async.wait_group 0;" ::: "memory");
}

// Split two fp32 into packed bf16 hi-pair and lo-pair (v ~= hi + lo, err ~2^-18).
__device__ __forceinline__ void split_pk(float v0, float v1, uint32_t& hi, uint32_t& lo) {
    uint32_t h;
    asm("cvt.rn.bf16x2.f32 %0, %1, %2;" : "=r"(h) : "f"(v1), "f"(v0));
    float h0f = __uint_as_float(h << 16);
    float h1f = __uint_as_float(h & 0xffff0000u);
    float l0 = v0 - h0f;
    float l1 = v1 - h1f;
    uint32_t l;
    asm("cvt.rn.bf16x2.f32 %0, %1, %2;" : "=r"(l) : "f"(l1), "f"(l0));
    hi = h;
    lo = l;
}

// m16n8k16 bf16 mma, C += A*B (fp32 accum).
__device__ __forceinline__ void mmabf(float* c, const uint32_t* a, const uint32_t* b) {
    asm volatile(
        "mma.sync.aligned.m16n8k16.row.col.f32.bf16.bf16.f32 "
        "{%0,%1,%2,%3}, {%4,%5,%6,%7}, {%8,%9}, {%0,%1,%2,%3};"
        : "+f"(c[0]), "+f"(c[1]), "+f"(c[2]), "+f"(c[3])
        : "r"(a[0]), "r"(a[1]), "r"(a[2]), "r"(a[3]), "r"(b[0]), "r"(b[1]));
}
// 3-term compensated product: C += (Ah+Al)*(Bh+Bl), dropping Al*Bl.
__device__ __forceinline__ void mma3(float* c, const uint32_t* ah, const uint32_t* al,
                                     const uint32_t* bh, const uint32_t* bl) {
    mmabf(c, al, bh);
    mmabf(c, ah, bl);
    mmabf(c, ah, bh);
}

// ldmatrix.x4
__device__ __forceinline__ void ldsm4(uint32_t addr, uint32_t* r) {
    asm volatile("ldmatrix.sync.aligned.m8n8.x4.shared.b16 {%0,%1,%2,%3}, [%4];"
        : "=r"(r[0]), "=r"(r[1]), "=r"(r[2]), "=r"(r[3])
        : "r"(addr));
}

// B hi+lo fragment pair via one LDSM.x4.
__device__ __forceinline__ void ldB4(uint32_t base, uint32_t lodelta, int W, int off_w,
                                     int lane, uint32_t* bh, uint32_t* bl) {
    uint32_t a = base + (uint32_t)off_w * 4u
               + (uint32_t)(lane & 7) * (uint32_t)(W * 4)
               + (uint32_t)((lane >> 3) & 1) * 16u
               + (uint32_t)((lane >> 4) & 1) * lodelta;
    uint32_t r[4];
    ldsm4(a, r);
    bh[0] = r[0]; bh[1] = r[1]; bl[0] = r[2]; bl[1] = r[3];
}

// A fragment via one LDSM.x4.
__device__ __forceinline__ void ldA4(uint32_t base, int W, int off_w, int lane, uint32_t* a) {
    uint32_t ad = base + (uint32_t)off_w * 4u
                + (uint32_t)((lane & 7) + ((lane >> 3) & 1) * 8) * (uint32_t)(W * 4)
                + (uint32_t)((lane >> 4) & 1) * 16u;
    ldsm4(ad, a);
}

// Feature S-chunk mma: 32 cols of S (4 j-tiles x 2 ksteps x mma3).
__device__ __forceinline__ void sfeat_chunk(
    uint32_t KTb, int c, int lane,
    const uint32_t QAh[2][4], const uint32_t QAl[2][4], float cS[4][4])
{
#pragma unroll
    for (int j = 0; j < 4; j++)
#pragma unroll
        for (int i = 0; i < 4; i++) cS[j][i] = 0.f;
#pragma unroll
    for (int kk = 0; kk < 2; kk++) {
#pragma unroll
        for (int j = 0; j < 4; j++) {
            uint32_t bh2[2], bl2[2];
            ldB4(KTb, 10240u, 20, (c * 4 + j) * 8 * 20 + kk * 8, lane, bh2, bl2);
            mma3(cS[j], QAh[kk], QAl[kk], bh2, bl2);
        }
    }
}

// ---------------------------------------------------------------------------
// Prep kernel: split all weights once into g_w (smem-staging layout).
// ---------------------------------------------------------------------------
__global__ void prep_kernel(
    const float* __restrict__ tqw, const float* __restrict__ tkw,
    const float* __restrict__ tvw, const float* __restrict__ tow,
    const float* __restrict__ fqw, const float* __restrict__ fkw,
    const float* __restrict__ fvw, const float* __restrict__ fow)
{
    int side = blockIdx.x >> 2, h = blockIdx.x & 3;
    const float* wq = side ? fqw : tqw;
    const float* wk = side ? fkw : tkw;
    const float* wv = side ? fvw : tvw;
    const float* wo = side ? fow : tow;
    uint32_t* dstw = (uint32_t*)&g_w[side][h][0];
    int tid = threadIdx.x;
    for (int i = tid; i < 96 * 32; i += 256) {
        int n = i % 96, dp = i / 96;
        const float* src = (n < 32) ? wq : (n < 64) ? wk : wv;
        int nn = n & 31;
        float v0 = src[(2 * dp) * 128 + h * 32 + nn];
        float v1 = src[(2 * dp + 1) * 128 + h * 32 + nn];
        split_pk(v0, v1, dstw[n * 36 + dp], dstw[3456 + n * 36 + dp]);
    }
    for (int i = tid; i < 64 * 16; i += 256) {
        int d = i & 63, kp = i >> 6;
        float v0 = wo[h * 2048 + (2 * kp) * 64 + d];
        float v1 = wo[h * 2048 + (2 * kp + 1) * 64 + d];
        split_pk(v0, v1, dstw[6912 + d * 20 + kp], dstw[8192 + d * 20 + kp]);
    }
}

// ---------------------------------------------------------------------------
// Feature body: id -> (b, t). 128 rows, 8 warps x 16 rows. atomicAdd into out.
// WC(h+1) prefetched via cp.async after the KV barrier (no register coupling).
// ---------------------------------------------------------------------------
__device__ __forceinline__ void feature_body(
    uint32_t* smw, int id,
    const float* __restrict__ x,
    const uint4* __restrict__ wsrc,
    const float* __restrict__ bq_g, const float* __restrict__ bk_g,
    const float* __restrict__ bv_g, const float* __restrict__ bo_g,
    float* __restrict__ out)
{
    uint32_t* XH  = smw;            // 128 x 36
    uint32_t* XL  = smw + 4608;
    uint32_t* KTH = smw + 18688;    // 128 x 20
    uint32_t* KTL = smw + 21248;
    uint32_t* VTH = smw + 23808;    // 32 x 68
    uint32_t* VTL = smw + 25984;    // -> 28160

    const uint32_t sb = (uint32_t)__cvta_generic_to_shared(smw);
    const uint32_t XHb = sb;                    // XL delta = 18432 B
    const uint32_t WCb = sb + 9216u * 4u;       // lo delta = 13824 B
    const uint32_t WOb = sb + 16128u * 4u;      // lo delta = 5120 B
    const uint32_t KTb = sb + 18688u * 4u;      // lo delta = 10240 B
    const uint32_t VTb = sb + 23808u * 4u;      // lo delta = 8704 B

    const int tid  = threadIdx.x;
    const int lane = tid & 31;
    const int w    = tid >> 5;
    const int g    = lane >> 2;
    const int t    = lane & 3;
    const int b    = id >> 6;
    const int tt   = id & 63;
    const int row0 = w * 16;
    const int rrA  = row0 + g, rrB = row0 + g + 8;

    // Stage x slice + WC(0)
    {
        const float* xp = x + (size_t)(b * TT + tt) * (FF * DD);
        for (int i = tid; i < FF * 32; i += 256) {
            int row = i >> 5, dp = i & 31;
            float2 v = *(const float2*)(xp + row * 64 + 2 * dp);
            split_pk(v.x, v.y, XH[row * 36 + dp], XL[row * 36 + dp]);
        }
        uint4* dstv = (uint4*)(smw + 9216);
        for (int i = tid; i < 1728; i += 256) dstv[i] = wsrc[i];
    }

    float oacc[8][4];
#pragma unroll
    for (int j = 0; j < 8; j++)
#pragma unroll
        for (int i = 0; i < 4; i++) oacc[j][i] = 0.f;

    for (int h = 0; h < HH; h++) {
        cp_wait0();        // WC(h) async prefetch complete (no-op for h=0)
        __syncthreads();   // WC(h)/x visible CTA-wide; prior head's WO reads done
        // Stage WO(h): LDG latency overlaps GEMM1 (WO read only after KV sync)
        {
            const uint4* srcv = wsrc + (size_t)h * 2368 + 1728;
            uint4* dstv = (uint4*)(smw + 16128);
            for (int i = tid; i < 640; i += 256) dstv[i] = srcv[i];
        }

        // --- GEMM1: [16 rows] x [k=64] x [n=96] ---
        float c12[12][4];
#pragma unroll
        for (int j = 0; j < 12; j++)
#pragma unroll
            for (int i = 0; i < 4; i++) c12[j][i] = 0.f;
        for (int kk = 0; kk < 4; kk++) {
            uint32_t ah[4], al[4];
            ldA4(XHb, 36, row0 * 36 + kk * 8, lane, ah);
            ldA4(XHb + 18432u, 36, row0 * 36 + kk * 8, lane, al);
#pragma unroll
            for (int j = 0; j < 12; j++) {
                uint32_t bh2[2], bl2[2];
                ldB4(WCb, 13824u, 36, j * 8 * 36 + kk * 8, lane, bh2, bl2);
                mma3(c12[j], ah, al, bh2, bl2);
            }
        }
        // Epilogue: Q -> regs, K -> smem, V -> smem transposed
        uint32_t QAh[2][4], QAl[2][4];
#pragma unroll
        for (int j = 0; j < 4; j++) {
            int cc = j * 8 + 2 * t;
            float b0 = bq_g[h * 32 + cc], b1 = bq_g[h * 32 + cc + 1];
            float v0 = (c12[j][0] + b0) * QSCALE, v1 = (c12[j][1] + b1) * QSCALE;
            float v2 = (c12[j][2] + b0) * QSCALE, v3 = (c12[j][3] + b1) * QSCALE;
            int kc = j >> 1, e = j & 1;
            split_pk(v0, v1, QAh[kc][2 * e],     QAl[kc][2 * e]);
            split_pk(v2, v3, QAh[kc][2 * e + 1], QAl[kc][2 * e + 1]);
        }
#pragma unroll
        for (int j = 4; j < 8; j++) {
            int cc = (j - 4) * 8 + 2 * t;
            float b0 = bk_g[h * 32 + cc], b1 = bk_g[h * 32 + cc + 1];
            int kp = cc >> 1;
            split_pk(c12[j][0] + b0, c12[j][1] + b1, KTH[rrA * 20 + kp], KTL[rrA * 20 + kp]);
            split_pk(c12[j][2] + b0, c12[j][3] + b1, KTH[rrB * 20 + kp], KTL[rrB * 20 + kp]);
        }
        {
            __nv_bfloat16* vh = reinterpret_cast<__nv_bfloat16*>(VTH);
            __nv_bfloat16* vl = reinterpret_cast<__nv_bfloat16*>(VTL);
#pragma unroll
            for (int j = 8; j < 12; j++) {
                int vk = (j - 8) * 8 + 2 * t;
                float b0 = bv_g[h * 32 + vk], b1 = bv_g[h * 32 + vk + 1];
                float vv[4] = {c12[j][0] + b0, c12[j][1] + b1, c12[j][2] + b0, c12[j][3] + b1};
                int   cl[4] = {vk, vk + 1, vk, vk + 1};
                int   rw[4] = {rrA, rrA, rrB, rrB};
#pragma unroll
                for (int q2 = 0; q2 < 4; q2++) {
                    __nv_bfloat16 hb = __float2bfloat16(vv[q2]);
                    float lf = vv[q2] - __bfloat162float(hb);
                    vh[cl[q2] * 136 + rw[q2]] = hb;
                    vl[cl[q2] * 136 + rw[q2]] = __float2bfloat16(lf);
                }
            }
        }
        __syncthreads();   // K/V + WO visible; GEMM1's WC reads complete

        // Prefetch WC(h+1) via cp.async: fully async under S/PV/outproj below.
        if (h < 3) {
            const uint4* srcv = wsrc + (size_t)(h + 1) * 2368;
            for (int i = tid; i < 1728; i += 256)
                cp_async16(WCb + (uint32_t)i * 16u, srcv + i);
            cp_commit();
        }

        // --- S = Q K^T, online softmax, fused PV; pipelined over 4 chunks ---
        float cP[4][4];
#pragma unroll
        for (int j = 0; j < 4; j++)
#pragma unroll
            for (int i = 0; i < 4; i++) cP[j][i] = 0.f;
        float mrA, mrB, sA, sB;
        float cSb[2][4][4];

        sfeat_chunk(KTb, 0, lane, QAh, QAl, cSb[0]);
#pragma unroll
        for (int c = 0; c < 4; c++) {
            float (*cS)[4] = cSb[c & 1];
            if (c < 3) sfeat_chunk(KTb, c + 1, lane, QAh, QAl, cSb[(c + 1) & 1]);

            float mA = cS[0][0], mB = cS[0][2];
#pragma unroll
            for (int j = 0; j < 4; j++) {
                mA = fmaxf(mA, fmaxf(cS[j][0], cS[j][1]));
                mB = fmaxf(mB, fmaxf(cS[j][2], cS[j][3]));
            }
            mA = fmaxf(mA, __shfl_xor_sync(0xffffffff, mA, 1));
            mA = fmaxf(mA, __shfl_xor_sync(0xffffffff, mA, 2));
            mB = fmaxf(mB, __shfl_xor_sync(0xffffffff, mB, 1));
            mB = fmaxf(mB, __shfl_xor_sync(0xffffffff, mB, 2));
            float nmA, nmB, chA = 0.f, chB = 0.f;
            if (c == 0) {
                nmA = mA; nmB = mB;
#pragma unroll
                for (int j = 0; j < 4; j++) {
                    cS[j][0] = ex2f(cS[j][0] - nmA); chA += cS[j][0];
                    cS[j][1] = ex2f(cS[j][1] - nmA); chA += cS[j][1];
                    cS[j][2] = ex2f(cS[j][2] - nmB); chB += cS[j][2];
                    cS[j][3] = ex2f(cS[j][3] - nmB); chB += cS[j][3];
                }
                sA = chA; sB = chB;
            } else {
                nmA = fmaxf(mrA, mA); nmB = fmaxf(mrB, mB);
                float scA = ex2f(mrA - nmA), scB = ex2f(mrB - nmB);
#pragma unroll
                for (int j = 0; j < 4; j++) {
                    cS[j][0] = ex2f(cS[j][0] - nmA); chA += cS[j][0];
                    cS[j][1] = ex2f(cS[j][1] - nmA); chA += cS[j][1];
                    cS[j][2] = ex2f(cS[j][2] - nmB); chB += cS[j][2];
                    cS[j][3] = ex2f(cS[j][3] - nmB); chB += cS[j][3];
                }
                sA = sA * scA + chA;
                sB = sB * scB + chB;
#pragma unroll
                for (int j = 0; j < 4; j++) {
                    cP[j][0] *= scA; cP[j][1] *= scA;
                    cP[j][2] *= scB; cP[j][3] *= scB;
                }
            }
            uint32_t ph[2][4], pl[2][4];
#pragma unroll
            for (int k0e = 0; k0e < 2; k0e++) {
                int j0 = 2 * k0e;
                split_pk(cS[j0][0],     cS[j0][1],     ph[k0e][0], pl[k0e][0]);
                split_pk(cS[j0][2],     cS[j0][3],     ph[k0e][1], pl[k0e][1]);
                split_pk(cS[j0 + 1][0], cS[j0 + 1][1], ph[k0e][2], pl[k0e][2]);
                split_pk(cS[j0 + 1][2], cS[j0 + 1][3], ph[k0e][3], pl[k0e][3]);
            }
#pragma unroll
            for (int k0e = 0; k0e < 2; k0e++) {
                int kkv = 2 * c + k0e;
#pragma unroll
                for (int j = 0; j < 4; j++) {
                    uint32_t bh2[2], bl2[2];
                    ldB4(VTb, 8704u, 68, j * 8 * 68 + kkv * 8, lane, bh2, bl2);
                    mma3(cP[j], ph[k0e], pl[k0e], bh2, bl2);
                }
            }
            mrA = nmA; mrB = nmB;
        }
        sA += __shfl_xor_sync(0xffffffff, sA, 1);
        sA += __shfl_xor_sync(0xffffffff, sA, 2);
        sB += __shfl_xor_sync(0xffffffff, sB, 1);
        sB += __shfl_xor_sync(0xffffffff, sB, 2);
        float invA = __fdividef(1.f, sA), invB = __fdividef(1.f, sB);
#pragma unroll
        for (int j = 0; j < 4; j++) {
            cP[j][0] *= invA; cP[j][1] *= invA;
            cP[j][2] *= invB; cP[j][3] *= invB;
        }

        // O -> regs, outproj accumulate
        uint32_t OAh[2][4], OAl[2][4];
#pragma unroll
        for (int j = 0; j < 4; j++) {
            int kc = j >> 1, e = j & 1;
            split_pk(cP[j][0], cP[j][1], OAh[kc][2 * e],     OAl[kc][2 * e]);
            split_pk(cP[j][2], cP[j][3], OAh[kc][2 * e + 1], OAl[kc][2 * e + 1]);
        }
#pragma unroll
        for (int kk = 0; kk < 2; kk++) {
#pragma unroll
            for (int j = 0; j < 8; j++) {
                uint32_t bh2[2], bl2[2];
                ldB4(WOb, 5120u, 20, j * 8 * 20 + kk * 8, lane, bh2, bl2);
                mma3(oacc[j], OAh[kk], OAl[kk], bh2, bl2);
            }
        }
    }

    // Deposit into out (zero-initialized by memset). rows = f, cols = d
#pragma unroll
    for (int j = 0; j < 8; j++) {
        int d0 = j * 8 + 2 * t;
        float bo0 = bo_g[d0], bo1 = bo_g[d0 + 1];
        size_t base0 = ((size_t)(b * TT + tt) * FF + rrA) * DD;
        size_t base1 = ((size_t)(b * TT + tt) * FF + rrB) * DD;
        atomicAdd(out + base0 + d0,     oacc[j][0] + bo0);
        atomicAdd(out + base0 + d0 + 1, oacc[j][1] + bo1);
        atomicAdd(out + base1 + d0,     oacc[j][2] + bo0);
        atomicAdd(out + base1 + d0 + 1, oacc[j][3] + bo1);
    }
}

// ---------------------------------------------------------------------------
// Temporal body: id -> (b, f-pair). 2 sub-blocks x 64 rows (T). atomicAdd out.
// ---------------------------------------------------------------------------
__device__ __forceinline__ void temporal_body(
    uint32_t* smw, int id,
    const float* __restrict__ x,
    const uint4* __restrict__ wsrc,
    const float* __restrict__ bq_g, const float* __restrict__ bk_g,
    const float* __restrict__ bv_g, const float* __restrict__ bo_g,
    float* __restrict__ out)
{
    uint32_t* XH  = smw;            // 2 x (64 x 36)
    uint32_t* XL  = smw + 4608;
    uint32_t* KTH = smw + 18688;    // 2 x (64 x 20)
    uint32_t* KTL = smw + 21248;
    uint32_t* VTH = smw + 23808;    // 2 x (32 x 36)
    uint32_t* VTL = smw + 26112;    // -> 28416

    const int tid  = threadIdx.x;
    const int lane = tid & 31;
    const int w    = tid >> 5;
    const int g    = lane >> 2;
    const int t    = lane & 3;
    const int b    = id >> 6;
    const int f0   = (id & 63) * 2;
    const int sub  = w >> 2;
    const int row0 = (w & 3) * 16;
    const int rrA  = row0 + g, rrB = row0 + g + 8;
    const int f    = f0 + sub;

    uint32_t* KTHs = KTH + sub * 1280;
    uint32_t* KTLs = KTL + sub * 1280;
    uint32_t* VTHs = VTH + sub * 1152;
    uint32_t* VTLs = VTL + sub * 1152;

    const uint32_t sb  = (uint32_t)__cvta_generic_to_shared(smw);
    const uint32_t XHb = sb + (uint32_t)(sub * 2304) * 4u;   // XL delta = 18432 B
    const uint32_t WCb = sb + 9216u * 4u;                    // lo delta = 13824 B
    const uint32_t WOb = sb + 16128u * 4u;                   // lo delta = 5120 B
    const uint32_t KTb = sb + (18688u + (uint32_t)(sub * 1280)) * 4u;  // lo delta 10240 B
    const uint32_t VTb = sb + (23808u + (uint32_t)(sub * 1152)) * 4u;  // lo delta 9216 B

    // Stage x slices + WC(0)
    for (int i = tid; i < 2 * 64 * 32; i += 256) {
        int s = i >> 11, rem = i & 2047, row = rem >> 5, dp = rem & 31;
        const float* xp = x + ((size_t)(b * TT + row) * FF + (f0 + s)) * DD;
        float2 v = *(const float2*)(xp + 2 * dp);
        split_pk(v.x, v.y, XH[s * 2304 + row * 36 + dp], XL[s * 2304 + row * 36 + dp]);
    }
    {
        uint4* dstv = (uint4*)(smw + 9216);
        for (int i = tid; i < 1728; i += 256) dstv[i] = wsrc[i];
    }

    float oacc[8][4];
#pragma unroll
    for (int j = 0; j < 8; j++)
#pragma unroll
        for (int i = 0; i < 4; i++) oacc[j][i] = 0.f;

    for (int h = 0; h < HH; h++) {
        cp_wait0();        // WC(h) async prefetch complete (no-op for h=0)
        __syncthreads();
        // Stage WO(h)
        {
            const uint4* srcv = wsrc + (size_t)h * 2368 + 1728;
            uint4* dstv = (uint4*)(smw + 16128);
            for (int i = tid; i < 640; i += 256) dstv[i] = srcv[i];
        }

        // --- GEMM1 ---
        float c12[12][4];
#pragma unroll
        for (int j = 0; j < 12; j++)
#pragma unroll
            for (int i = 0; i < 4; i++) c12[j][i] = 0.f;
        for (int kk = 0; kk < 4; kk++) {
            uint32_t ah[4], al[4];
            ldA4(XHb, 36, row0 * 36 + kk * 8, lane, ah);
            ldA4(XHb + 18432u, 36, row0 * 36 + kk * 8, lane, al);
#pragma unroll
            for (int j = 0; j < 12; j++) {
                uint32_t bh2[2], bl2[2];
                ldB4(WCb, 13824u, 36, j * 8 * 36 + kk * 8, lane, bh2, bl2);
                mma3(c12[j], ah, al, bh2, bl2);
            }
        }
        uint32_t QAh[2][4], QAl[2][4];
#pragma unroll
        for (int j = 0; j < 4; j++) {
            int cc = j * 8 + 2 * t;
            float b0 = bq_g[h * 32 + cc], b1 = bq_g[h * 32 + cc + 1];
            float v0 = (c12[j][0] + b0) * QSCALE, v1 = (c12[j][1] + b1) * QSCALE;
            float v2 = (c12[j][2] + b0) * QSCALE, v3 = (c12[j][3] + b1) * QSCALE;
            int kc = j >> 1, e = j & 1;
            split_pk(v0, v1, QAh[kc][2 * e],     QAl[kc][2 * e]);
            split_pk(v2, v3, QAh[kc][2 * e + 1], QAl[kc][2 * e + 1]);
        }
#pragma unroll
        for (int j = 4; j < 8; j++) {
            int cc = (j - 4) * 8 + 2 * t;
            float b0 = bk_g[h * 32 + cc], b1 = bk_g[h * 32 + cc + 1];
            int kp = cc >> 1;
            split_pk(c12[j][0] + b0, c12[j][1] + b1, KTHs[rrA * 20 + kp], KTLs[rrA * 20 + kp]);
            split_pk(c12[j][2] + b0, c12[j][3] + b1, KTHs[rrB * 20 + kp], KTLs[rrB * 20 + kp]);
        }
        {
            __nv_bfloat16* vh = reinterpret_cast<__nv_bfloat16*>(VTHs);
            __nv_bfloat16* vl = reinterpret_cast<__nv_bfloat16*>(VTLs);
#pragma unroll
            for (int j = 8; j < 12; j++) {
                int vk = (j - 8) * 8 + 2 * t;
                float b0 = bv_g[h * 32 + vk], b1 = bv_g[h * 32 + vk + 1];
                float vv[4] = {c12[j][0] + b0, c12[j][1] + b1, c12[j][2] + b0, c12[j][3] + b1};
                int   cl[4] = {vk, vk + 1, vk, vk + 1};
                int   rw[4] = {rrA, rrA, rrB, rrB};
#pragma unroll
                for (int q2 = 0; q2 < 4; q2++) {
                    __nv_bfloat16 hb = __float2bfloat16(vv[q2]);
                    float lf = vv[q2] - __bfloat162float(hb);
                    vh[cl[q2] * 72 + rw[q2]] = hb;
                    vl[cl[q2] * 72 + rw[q2]] = __float2bfloat16(lf);
                }
            }
        }
        __syncthreads();   // CTA-wide: K/V + WO visible, WC reads complete

        // Prefetch WC(h+1) via cp.async under S/PV/outproj below.
        if (h < 3) {
            const uint4* srcv = wsrc + (size_t)(h + 1) * 2368;
            for (int i = tid; i < 1728; i += 256)
                cp_async16(WCb + (uint32_t)i * 16u, srcv + i);
            cp_commit();
        }

        // --- S = Q K^T over 64 cols, full-row softmax ---
        float cS[8][4];
#pragma unroll
        for (int j = 0; j < 8; j++)
#pragma unroll
            for (int i = 0; i < 4; i++) cS[j][i] = 0.f;
#pragma unroll
        for (int kk = 0; kk < 2; kk++) {
#pragma unroll
            for (int j = 0; j < 8; j++) {
                uint32_t bh2[2], bl2[2];
                ldB4(KTb, 10240u, 20, j * 8 * 20 + kk * 8, lane, bh2, bl2);
                mma3(cS[j], QAh[kk], QAl[kk], bh2, bl2);
            }
        }
        float mA = cS[0][0], mB = cS[0][2];
#pragma unroll
        for (int j = 0; j < 8; j++) {
            mA = fmaxf(mA, fmaxf(cS[j][0], cS[j][1]));
            mB = fmaxf(mB, fmaxf(cS[j][2], cS[j][3]));
        }
        mA = fmaxf(mA, __shfl_xor_sync(0xffffffff, mA, 1));
        mA = fmaxf(mA, __shfl_xor_sync(0xffffffff, mA, 2));
        mB = fmaxf(mB, __shfl_xor_sync(0xffffffff, mB, 1));
        mB = fmaxf(mB, __shfl_xor_sync(0xffffffff, mB, 2));
        float sA = 0.f, sB = 0.f;
#pragma unroll
        for (int j = 0; j < 8; j++) {
            cS[j][0] = ex2f(cS[j][0] - mA); sA += cS[j][0];
            cS[j][1] = ex2f(cS[j][1] - mA); sA += cS[j][1];
            cS[j][2] = ex2f(cS[j][2] - mB); sB += cS[j][2];
            cS[j][3] = ex2f(cS[j][3] - mB); sB += cS[j][3];
        }
        sA += __shfl_xor_sync(0xffffffff, sA, 1);
        sA += __shfl_xor_sync(0xffffffff, sA, 2);
        sB += __shfl_xor_sync(0xffffffff, sB, 1);
        sB += __shfl_xor_sync(0xffffffff, sB, 2);
        float invA = __fdividef(1.f, sA), invB = __fdividef(1.f, sB);

        // P -> regs (A-frags for PV)
        uint32_t PAh[4][4], PAl[4][4];
#pragma unroll
        for (int kc = 0; kc < 4; kc++) {
            int j0 = 2 * kc;
            split_pk(cS[j0][0] * invA,     cS[j0][1] * invA,     PAh[kc][0], PAl[kc][0]);
            split_pk(cS[j0][2] * invB,     cS[j0][3] * invB,     PAh[kc][1], PAl[kc][1]);
            split_pk(cS[j0 + 1][0] * invA, cS[j0 + 1][1] * invA, PAh[kc][2], PAl[kc][2]);
            split_pk(cS[j0 + 1][2] * invB, cS[j0 + 1][3] * invB, PAh[kc][3], PAl[kc][3]);
        }

        // --- PV ---
        float cP[4][4];
#pragma unroll
        for (int j = 0; j < 4; j++)
#pragma unroll
            for (int i = 0; i < 4; i++) cP[j][i] = 0.f;
#pragma unroll
        for (int kk = 0; kk < 4; kk++) {
#pragma unroll
            for (int j = 0; j < 4; j++) {
                uint32_t bh2[2], bl2[2];
                ldB4(VTb, 9216u, 36, j * 8 * 36 + kk * 8, lane, bh2, bl2);
                mma3(cP[j], PAh[kk], PAl[kk], bh2, bl2);
            }
        }

        // O -> regs, outproj accumulate
        uint32_t OAh[2][4], OAl[2][4];
#pragma unroll
        for (int j = 0; j < 4; j++) {
            int kc = j >> 1, e = j & 1;
            split_pk(cP[j][0], cP[j][1], OAh[kc][2 * e],     OAl[kc][2 * e]);
            split_pk(cP[j][2], cP[j][3], OAh[kc][2 * e + 1], OAl[kc][2 * e + 1]);
        }
#pragma unroll
        for (int kk = 0; kk < 2; kk++) {
#pragma unroll
            for (int j = 0; j < 8; j++) {
                uint32_t bh2[2], bl2[2];
                ldB4(WOb, 5120u, 20, j * 8 * 20 + kk * 8, lane, bh2, bl2);
                mma3(oacc[j], OAh[kk], OAl[kk], bh2, bl2);
            }
        }
    }

    // Deposit into out. rows = t, cols = d
#pragma unroll
    for (int j = 0; j < 8; j++) {
        int d0 = j * 8 + 2 * t;
        float bo0 = bo_g[d0], bo1 = bo_g[d0 + 1];
        size_t base0 = ((size_t)(b * TT + rrA) * FF + f) * DD;
        size_t base1 = ((size_t)(b * TT + rrB) * FF + f) * DD;
        atomicAdd(out + base0 + d0,     oacc[j][0] + bo0);
        atomicAdd(out + base0 + d0 + 1, oacc[j][1] + bo1);
        atomicAdd(out + base1 + d0,     oacc[j][2] + bo0);
        atomicAdd(out + base1 + d0 + 1, oacc[j][3] + bo1);
    }
}

// ---------------------------------------------------------------------------
// Fused kernel: even blocks -> temporal, odd blocks -> feature (interleaved).
// ---------------------------------------------------------------------------
__global__ __launch_bounds__(256, 2) void fused_kernel(
    const float* __restrict__ x,
    const float* __restrict__ tqb, const float* __restrict__ tkb,
    const float* __restrict__ tvb, const float* __restrict__ tob,
    const float* __restrict__ fqb, const float* __restrict__ fkb,
    const float* __restrict__ fvb, const float* __restrict__ fob,
    float* __restrict__ out)
{
    extern __shared__ uint32_t smw[];
    int id = blockIdx.x >> 1;
    if ((blockIdx.x & 1) == 0) {
        temporal_body(smw, id, x, &g_w[0][0][0], tqb, tkb, tvb, tob, out);
    } else {
        feature_body(smw, id, x, &g_w[1][0][0], fqb, fkb, fvb, fob, out);
    }
}

extern "C" void kernel_launch(void* const* d_in, const int* in_sizes, int n_in,
                              void* d_out, int out_size)
{
    const float* x = (const float*)d_in[0];
    const float *tqw, *tqb, *tkw, *tkb, *tvw, *tvb, *tow, *tob;
    const float *fqw, *fqb, *fkw, *fkb, *fvw, *fvb, *fow, *fob;

    if (in_sizes[8] == 64) {  // reference-signature order
        tqw = (const float*)d_in[1];  tqb = (const float*)d_in[2];
        tkw = (const float*)d_in[3];  tkb = (const float*)d_in[4];
        tvw = (const float*)d_in[5];  tvb = (const float*)d_in[6];
        tow = (const float*)d_in[7];  tob = (const float*)d_in[8];
        fqw = (const float*)d_in[9];  fqb = (const float*)d_in[10];
        fkw = (const float*)d_in[11]; fkb = (const float*)d_in[12];
        fvw = (const float*)d_in[13]; fvb = (const float*)d_in[14];
        fow = (const float*)d_in[15]; fob = (const float*)d_in[16];
    } else {                  // setup_inputs dict order
        tqw = (const float*)d_in[1];  tqb = (const float*)d_in[2];
        tkw = (const float*)d_in[3];  tkb = (const float*)d_in[4];
        tvw = (const float*)d_in[5];  tvb = (const float*)d_in[6];
        fqw = (const float*)d_in[7];  fqb = (const float*)d_in[8];
        fkw = (const float*)d_in[9];  fkb = (const float*)d_in[10];
        fvw = (const float*)d_in[11]; fvb = (const float*)d_in[12];
        tow = (const float*)d_in[13]; tob = (const float*)d_in[14];
        fow = (const float*)d_in[15]; fob = (const float*)d_in[16];
    }

    const int SMEM = 28416 * 4;     // 113664 B -> 2 CTA/SM
    cudaFuncSetAttribute(fused_kernel,
                         cudaFuncAttributeMaxDynamicSharedMemorySize, SMEM);

    cudaMemsetAsync(d_out, 0, (size_t)out_size * sizeof(float), 0);
    prep_kernel<<<8, 256>>>(tqw, tkw, tvw, tow, fqw, fkw, fvw, fow);
    fused_kernel<<<4096, 256, SMEM>>>(
        x, tqb, tkb, tvb, tob, fqb, fkb, fvb, fob, (float*)d_out);
}